// round 3
// baseline (speedup 1.0000x reference)
#include <cuda_runtime.h>
#include <math.h>

#define TPB 256

// ---- problem sizes ----
constexpr int NB  = 4096;   // batch
constexpr int DIN = 1024;
constexpr int DD  = 256;
constexpr int KK  = 1024;   // clusters
constexpr int LL  = 32768;  // queue_n rows
constexpr int QKR = 4096;   // queue_k rows

constexpr int NSEG = 8;             // split-B segments for agg GEMM
constexpr int SEGB = NB / NSEG;     // 512
constexpr int NCHN = 16, TPCN = 16; // loss_n: 16 chunks x 16 tiles x 128 = 32768
constexpr int NCHK = 8,  TPCK = 4;  // loss_k:  8 chunks x  4 tiles x 128 = 4096
constexpr int CSCH = 32;            // colsum b-chunks

constexpr float INVT = 1.0f / 0.07f;

// ---- scratch offsets (floats) ----
constexpr size_t O_TMP    = 0;
constexpr size_t O_FEAT1  = O_TMP    + (size_t)NB*DD;
constexpr size_t O_CTX1   = O_FEAT1  + (size_t)NB*DD;
constexpr size_t O_CTX2   = O_CTX1   + (size_t)KK*DD;
constexpr size_t O_QN     = O_CTX2   + (size_t)KK*DD;
constexpr size_t O_QKQ    = O_QN     + (size_t)LL*DD;
constexpr size_t O_LOGITS = O_QKQ    + (size_t)QKR*DD;
constexpr size_t O_ASSIGN = O_LOGITS + (size_t)NB*KK;
constexpr size_t O_AGGK1  = O_ASSIGN + (size_t)NB*KK;
constexpr size_t O_AGGP   = O_AGGK1  + (size_t)KK*DD;
constexpr size_t O_CSP    = O_AGGP   + (size_t)NSEG*KK*DD;
constexpr size_t O_NORMK  = O_CSP    + (size_t)CSCH*KK;
constexpr size_t O_LPN    = O_NORMK  + KK;
constexpr size_t O_LPK    = O_LPN    + NB;
constexpr size_t O_PARTN  = O_LPK    + KK;
constexpr size_t O_PARTK  = O_PARTN  + (size_t)NB*NCHN;
constexpr size_t O_END    = O_PARTK  + (size_t)KK*NCHK;

__device__ float g_scratch[O_END];

// ---------------- helpers ----------------
__device__ __forceinline__ float gumbelf(float u) {
    u = u * (1.0f - 2e-6f) + 1e-6f;
    return -logf(-logf(u));            // accurate: feeds argmax/softmax peaks
}

__device__ __forceinline__ float blocksum256(float v) {
    __shared__ float sh_s[8];
    #pragma unroll
    for (int o = 16; o; o >>= 1) v += __shfl_xor_sync(0xffffffffu, v, o);
    if ((threadIdx.x & 31) == 0) sh_s[threadIdx.x >> 5] = v;
    __syncthreads();
    float s = 0.f;
    #pragma unroll
    for (int i = 0; i < 8; i++) s += sh_s[i];
    __syncthreads();
    return s;
}

__device__ __forceinline__ float blockmax256(float v) {
    __shared__ float sh_m[8];
    #pragma unroll
    for (int o = 16; o; o >>= 1) v = fmaxf(v, __shfl_xor_sync(0xffffffffu, v, o));
    if ((threadIdx.x & 31) == 0) sh_m[threadIdx.x >> 5] = v;
    __syncthreads();
    float s = sh_m[0];
    #pragma unroll
    for (int i = 1; i < 8; i++) s = fmaxf(s, sh_m[i]);
    __syncthreads();
    return s;
}

// ---------------- row L2 normalize (D = 256 = blockDim) ----------------
__global__ void k_rownorm(const float* __restrict__ src, float* __restrict__ dst) {
    int r = blockIdx.x, t = threadIdx.x;
    float v = src[(size_t)r * DD + t];
    float s = blocksum256(v * v);
    dst[(size_t)r * DD + t] = v * rsqrtf(fmaxf(s, 1e-12f));
}

// queue = l2norm(queue_k + qnoise + queue_k)
__global__ void k_rownorm_queue(const float* __restrict__ qk, const float* __restrict__ nz,
                                float* __restrict__ dst) {
    int r = blockIdx.x, t = threadIdx.x;
    size_t i = (size_t)r * DD + t;
    float v = (qk[i] + nz[i]) + qk[i];
    float s = blocksum256(v * v);
    dst[i] = v * rsqrtf(fmaxf(s, 1e-12f));
}

// ---------------- GEMM NN: C[M,N] = A[M,Kd] @ B[Kd,N] ----------------
__global__ void __launch_bounds__(TPB) k_gemm_nn(
    const float* __restrict__ A, const float* __restrict__ Bm,
    float* __restrict__ C, int Kd, int N) {
    __shared__ float As[16][132];
    __shared__ float Bs[16][132];
    const int tid = threadIdx.x;
    const int tx = tid & 15, ty = tid >> 4;
    const int m0 = blockIdx.x * 128, n0 = blockIdx.y * 128;
    float acc[8][8];
    #pragma unroll
    for (int i = 0; i < 8; i++)
        #pragma unroll
        for (int j = 0; j < 8; j++) acc[i][j] = 0.f;
    for (int k0 = 0; k0 < Kd; k0 += 16) {
        #pragma unroll
        for (int p = 0; p < 2; p++) {
            int i = tid + p * TPB;
            int r = i >> 2, v = i & 3;
            float4 q = *(const float4*)(A + (size_t)(m0 + r) * Kd + k0 + v * 4);
            As[v*4+0][r] = q.x; As[v*4+1][r] = q.y; As[v*4+2][r] = q.z; As[v*4+3][r] = q.w;
        }
        #pragma unroll
        for (int p = 0; p < 2; p++) {
            int i = tid + p * TPB;
            int kk = i >> 5, v = i & 31;
            *(float4*)(&Bs[kk][v*4]) = *(const float4*)(Bm + (size_t)(k0 + kk) * N + n0 + v * 4);
        }
        __syncthreads();
        #pragma unroll
        for (int kk = 0; kk < 16; kk++) {
            float a[8], b[8];
            *(float4*)(a)     = *(const float4*)(&As[kk][ty * 8]);
            *(float4*)(a + 4) = *(const float4*)(&As[kk][ty * 8 + 4]);
            *(float4*)(b)     = *(const float4*)(&Bs[kk][tx * 8]);
            *(float4*)(b + 4) = *(const float4*)(&Bs[kk][tx * 8 + 4]);
            #pragma unroll
            for (int i = 0; i < 8; i++)
                #pragma unroll
                for (int j = 0; j < 8; j++) acc[i][j] += a[i] * b[j];
        }
        __syncthreads();
    }
    #pragma unroll
    for (int i = 0; i < 8; i++) {
        float* cp = C + (size_t)(m0 + ty * 8 + i) * N + n0 + tx * 8;
        *(float4*)cp       = make_float4(acc[i][0], acc[i][1], acc[i][2], acc[i][3]);
        *(float4*)(cp + 4) = make_float4(acc[i][4], acc[i][5], acc[i][6], acc[i][7]);
    }
}

// ---------------- GEMM NT: C[M,N] = A[M,256] @ B[N,256]^T ----------------
__global__ void __launch_bounds__(TPB) k_gemm_nt(
    const float* __restrict__ A, const float* __restrict__ Bm,
    float* __restrict__ C, int N) {
    __shared__ float As[16][132];
    __shared__ float Bs[16][132];
    const int tid = threadIdx.x;
    const int tx = tid & 15, ty = tid >> 4;
    const int m0 = blockIdx.x * 128, n0 = blockIdx.y * 128;
    float acc[8][8];
    #pragma unroll
    for (int i = 0; i < 8; i++)
        #pragma unroll
        for (int j = 0; j < 8; j++) acc[i][j] = 0.f;
    for (int k0 = 0; k0 < DD; k0 += 16) {
        #pragma unroll
        for (int p = 0; p < 2; p++) {
            int i = tid + p * TPB;
            int r = i >> 2, v = i & 3;
            float4 q = *(const float4*)(A + (size_t)(m0 + r) * DD + k0 + v * 4);
            As[v*4+0][r] = q.x; As[v*4+1][r] = q.y; As[v*4+2][r] = q.z; As[v*4+3][r] = q.w;
        }
        #pragma unroll
        for (int p = 0; p < 2; p++) {
            int i = tid + p * TPB;
            int n = i >> 2, v = i & 3;
            float4 q = *(const float4*)(Bm + (size_t)(n0 + n) * DD + k0 + v * 4);
            Bs[v*4+0][n] = q.x; Bs[v*4+1][n] = q.y; Bs[v*4+2][n] = q.z; Bs[v*4+3][n] = q.w;
        }
        __syncthreads();
        #pragma unroll
        for (int kk = 0; kk < 16; kk++) {
            float a[8], b[8];
            *(float4*)(a)     = *(const float4*)(&As[kk][ty * 8]);
            *(float4*)(a + 4) = *(const float4*)(&As[kk][ty * 8 + 4]);
            *(float4*)(b)     = *(const float4*)(&Bs[kk][tx * 8]);
            *(float4*)(b + 4) = *(const float4*)(&Bs[kk][tx * 8 + 4]);
            #pragma unroll
            for (int i = 0; i < 8; i++)
                #pragma unroll
                for (int j = 0; j < 8; j++) acc[i][j] += a[i] * b[j];
        }
        __syncthreads();
    }
    #pragma unroll
    for (int i = 0; i < 8; i++) {
        float* cp = C + (size_t)(m0 + ty * 8 + i) * N + n0 + tx * 8;
        *(float4*)cp       = make_float4(acc[i][0], acc[i][1], acc[i][2], acc[i][3]);
        *(float4*)(cp + 4) = make_float4(acc[i][4], acc[i][5], acc[i][6], acc[i][7]);
    }
}

// -------- GEMM TN split-B: Cpart[z] = assign[seg z]^T @ feat ----------
__global__ void __launch_bounds__(TPB) k_gemm_tn_seg(
    const float* __restrict__ Asg, const float* __restrict__ Fm,
    float* __restrict__ Cpart) {
    __shared__ float As[16][132];
    __shared__ float Bs[16][132];
    const int tid = threadIdx.x;
    const int tx = tid & 15, ty = tid >> 4;
    const int m0 = blockIdx.x * 128;   // cluster dim
    const int n0 = blockIdx.y * 128;   // feature dim
    const int z  = blockIdx.z;
    float acc[8][8];
    #pragma unroll
    for (int i = 0; i < 8; i++)
        #pragma unroll
        for (int j = 0; j < 8; j++) acc[i][j] = 0.f;
    for (int b0 = z * SEGB; b0 < (z + 1) * SEGB; b0 += 16) {
        #pragma unroll
        for (int p = 0; p < 2; p++) {
            int i = tid + p * TPB;
            int bb = i >> 5, v = i & 31;
            *(float4*)(&As[bb][v*4]) = *(const float4*)(Asg + (size_t)(b0 + bb) * KK + m0 + v * 4);
        }
        #pragma unroll
        for (int p = 0; p < 2; p++) {
            int i = tid + p * TPB;
            int bb = i >> 5, v = i & 31;
            *(float4*)(&Bs[bb][v*4]) = *(const float4*)(Fm + (size_t)(b0 + bb) * DD + n0 + v * 4);
        }
        __syncthreads();
        #pragma unroll
        for (int bb = 0; bb < 16; bb++) {
            float a[8], b[8];
            *(float4*)(a)     = *(const float4*)(&As[bb][ty * 8]);
            *(float4*)(a + 4) = *(const float4*)(&As[bb][ty * 8 + 4]);
            *(float4*)(b)     = *(const float4*)(&Bs[bb][tx * 8]);
            *(float4*)(b + 4) = *(const float4*)(&Bs[bb][tx * 8 + 4]);
            #pragma unroll
            for (int i = 0; i < 8; i++)
                #pragma unroll
                for (int j = 0; j < 8; j++) acc[i][j] += a[i] * b[j];
        }
        __syncthreads();
    }
    #pragma unroll
    for (int i = 0; i < 8; i++) {
        float* cp = Cpart + (size_t)z * KK * DD + (size_t)(m0 + ty * 8 + i) * DD + n0 + tx * 8;
        *(float4*)cp       = make_float4(acc[i][0], acc[i][1], acc[i][2], acc[i][3]);
        *(float4*)(cp + 4) = make_float4(acc[i][4], acc[i][5], acc[i][6], acc[i][7]);
    }
}

// ---- fused negatives GEMM + streaming exp-sum (fixed shift = 1/T) ----
__global__ void __launch_bounds__(TPB) k_expsum(
    const float* __restrict__ Am, const float* __restrict__ Qm,
    float* __restrict__ part, int tpc, int nch) {
    __shared__ float As[16][132];
    __shared__ float Bs[16][132];
    const int tid = threadIdx.x;
    const int tx = tid & 15, ty = tid >> 4;
    const int m0 = blockIdx.x * 128;
    const int chunk = blockIdx.y;
    float rp[8];
    #pragma unroll
    for (int i = 0; i < 8; i++) rp[i] = 0.f;
    for (int t = 0; t < tpc; t++) {
        const int n0 = (chunk * tpc + t) * 128;
        float acc[8][8];
        #pragma unroll
        for (int i = 0; i < 8; i++)
            #pragma unroll
            for (int j = 0; j < 8; j++) acc[i][j] = 0.f;
        for (int k0 = 0; k0 < DD; k0 += 16) {
            #pragma unroll
            for (int p = 0; p < 2; p++) {
                int i = tid + p * TPB;
                int r = i >> 2, v = i & 3;
                float4 q = *(const float4*)(Am + (size_t)(m0 + r) * DD + k0 + v * 4);
                As[v*4+0][r] = q.x; As[v*4+1][r] = q.y; As[v*4+2][r] = q.z; As[v*4+3][r] = q.w;
            }
            #pragma unroll
            for (int p = 0; p < 2; p++) {
                int i = tid + p * TPB;
                int n = i >> 2, v = i & 3;
                float4 q = *(const float4*)(Qm + (size_t)(n0 + n) * DD + k0 + v * 4);
                Bs[v*4+0][n] = q.x; Bs[v*4+1][n] = q.y; Bs[v*4+2][n] = q.z; Bs[v*4+3][n] = q.w;
            }
            __syncthreads();
            #pragma unroll
            for (int kk = 0; kk < 16; kk++) {
                float a[8], b[8];
                *(float4*)(a)     = *(const float4*)(&As[kk][ty * 8]);
                *(float4*)(a + 4) = *(const float4*)(&As[kk][ty * 8 + 4]);
                *(float4*)(b)     = *(const float4*)(&Bs[kk][tx * 8]);
                *(float4*)(b + 4) = *(const float4*)(&Bs[kk][tx * 8 + 4]);
                #pragma unroll
                for (int i = 0; i < 8; i++)
                    #pragma unroll
                    for (int j = 0; j < 8; j++) acc[i][j] += a[i] * b[j];
            }
            __syncthreads();
        }
        #pragma unroll
        for (int i = 0; i < 8; i++) {
            float s = 0.f;
            #pragma unroll
            for (int j = 0; j < 8; j++) s += __expf(acc[i][j] * INVT - INVT);
            rp[i] += s;
        }
    }
    // reduce over the 16 col-threads per row (reuse As: need 2048 <= 2112)
    float* red = &As[0][0];
    #pragma unroll
    for (int i = 0; i < 8; i++) red[(ty * 8 + i) * 16 + tx] = rp[i];
    __syncthreads();
    if (tid < 128) {
        float s = 0.f;
        #pragma unroll
        for (int x = 0; x < 16; x++) s += red[tid * 16 + x];
        part[(size_t)(m0 + tid) * nch + chunk] = s;
    }
}

// ---------------- gumbel softmax (soft) over K=1024 ----------------
__global__ void k_softmax(const float* __restrict__ logits, const float* __restrict__ u,
                          float* __restrict__ assign) {
    int r = blockIdx.x, t = threadIdx.x;
    float z[4];
    #pragma unroll
    for (int j = 0; j < 4; j++) {
        int k = j * 256 + t;
        size_t i = (size_t)r * KK + k;
        z[j] = (logits[i] + gumbelf(u[i])) * 2.0f;   // 1/GUMBEL_TEMP
    }
    float m = fmaxf(fmaxf(z[0], z[1]), fmaxf(z[2], z[3]));
    m = blockmax256(m);
    float s = 0.f;
    #pragma unroll
    for (int j = 0; j < 4; j++) { z[j] = __expf(z[j] - m); s += z[j]; }
    s = blocksum256(s);
    float inv = 1.0f / s;
    #pragma unroll
    for (int j = 0; j < 4; j++) {
        int k = j * 256 + t;
        assign[(size_t)r * KK + k] = z[j] * inv;
    }
}

// ---------------- hard-path argmax(logits + gumbel), first-index ties ----
__global__ void k_argmax(const float* __restrict__ logits, const float* __restrict__ u,
                         float* __restrict__ out) {
    __shared__ float sb[8]; __shared__ int si[8];
    int r = blockIdx.x, t = threadIdx.x;
    float best = -1e30f; int bi = 0;
    #pragma unroll
    for (int j = 0; j < 4; j++) {
        int k = j * 256 + t;
        size_t i = (size_t)r * KK + k;
        float z = logits[i] + gumbelf(u[i]);
        if (z > best) { best = z; bi = k; }
    }
    #pragma unroll
    for (int o = 16; o; o >>= 1) {
        float ob = __shfl_xor_sync(0xffffffffu, best, o);
        int   oi = __shfl_xor_sync(0xffffffffu, bi, o);
        if (ob > best || (ob == best && oi < bi)) { best = ob; bi = oi; }
    }
    if ((t & 31) == 0) { sb[t >> 5] = best; si[t >> 5] = bi; }
    __syncthreads();
    if (t == 0) {
        #pragma unroll
        for (int w = 1; w < 8; w++)
            if (sb[w] > best || (sb[w] == best && si[w] < bi)) { best = sb[w]; bi = si[w]; }
        out[r] = (float)bi;
    }
}

// ---------------- column sums of assign (normalizer) ----------------
__global__ void k_colsum_part(const float* __restrict__ assign, float* __restrict__ csp) {
    int k = blockIdx.x * TPB + threadIdx.x;
    int c = blockIdx.y;
    float s = 0.f;
    #pragma unroll 4
    for (int b = c * (NB / CSCH); b < (c + 1) * (NB / CSCH); b++)
        s += assign[(size_t)b * KK + k];
    csp[(size_t)c * KK + k] = s;
}
__global__ void k_colsum_fin(const float* __restrict__ csp, float* __restrict__ norm) {
    int k = blockIdx.x * TPB + threadIdx.x;
    float s = 0.f;
    #pragma unroll
    for (int c = 0; c < CSCH; c++) s += csp[(size_t)c * KK + k];
    norm[k] = s;
}

// ---------------- agg_k finish: sum partials, /norm, L2 normalize ----------
__global__ void k_aggk_finish(const float* __restrict__ part, const float* __restrict__ norm,
                              float* __restrict__ dst) {
    int r = blockIdx.x, t = threadIdx.x;
    float v = 0.f;
    #pragma unroll
    for (int s = 0; s < NSEG; s++) v += part[(size_t)s * KK * DD + (size_t)r * DD + t];
    v = v / (norm[r] + 1e-8f);
    float ss = blocksum256(v * v);
    dst[(size_t)r * DD + t] = v * rsqrtf(fmaxf(ss, 1e-12f));
}

// ------------- per-row CE: lp = lpos/T - logsumexp (shifted) -------------
__global__ void k_ce_row(const float* __restrict__ q, const float* __restrict__ kv,
                         const float* __restrict__ part, int nch,
                         float* __restrict__ lp) {
    int r = blockIdx.x, t = threadIdx.x;
    float v = q[(size_t)r * DD + t] * kv[(size_t)r * DD + t];
    float lpos = blocksum256(v);
    if (t == 0) {
        float S = expf(lpos * INVT - INVT);
        for (int c = 0; c < nch; c++) S += part[(size_t)r * nch + c];
        lp[r] = lpos * INVT - INVT - logf(S);
    }
}

// ---------------- final scalar loss ----------------
__global__ void k_loss(const float* __restrict__ lpn, const float* __restrict__ lpk,
                       float* __restrict__ out) {
    int t = threadIdx.x;
    float s1 = 0.f;
    for (int i = t; i < NB; i += TPB) s1 += lpn[i];
    s1 = blocksum256(s1);
    float s2 = 0.f;
    for (int i = t; i < KK; i += TPB) s2 += lpk[i];
    s2 = blocksum256(s2);
    if (t == 0) out[0] = -(s1 / NB) - (s2 / KK);
}

// ============================ launcher ============================
extern "C" void kernel_launch(void* const* d_in, const int* in_sizes, int n_in,
                              void* d_out, int out_size) {
    const float* x1    = (const float*)d_in[0];
    const float* x2    = (const float*)d_in[1];
    const float* W1    = (const float*)d_in[2];
    const float* W2    = (const float*)d_in[3];
    const float* ctx1r = (const float*)d_in[4];
    const float* ctx2r = (const float*)d_in[5];
    const float* qn_r  = (const float*)d_in[6];
    const float* qk_r  = (const float*)d_in[7];
    const float* u1a   = (const float*)d_in[8];
    const float* u1b   = (const float*)d_in[9];
    const float* u2a   = (const float*)d_in[10];
    const float* u2b   = (const float*)d_in[11];
    const float* qnz   = (const float*)d_in[12];
    (void)u2b; (void)in_sizes; (void)n_in; (void)out_size;

    float* S;
    cudaGetSymbolAddress((void**)&S, g_scratch);
    float* tmp    = S + O_TMP;
    float* feat1  = S + O_FEAT1;
    float* ctx1   = S + O_CTX1;
    float* ctx2   = S + O_CTX2;
    float* qn     = S + O_QN;
    float* qkq    = S + O_QKQ;
    float* logits = S + O_LOGITS;
    float* assign = S + O_ASSIGN;
    float* aggk1  = S + O_AGGK1;
    float* aggp   = S + O_AGGP;
    float* csp    = S + O_CSP;
    float* normk  = S + O_NORMK;
    float* lpn    = S + O_LPN;
    float* lpk    = S + O_LPK;
    float* partn  = S + O_PARTN;
    float* partk  = S + O_PARTK;

    float* outF     = (float*)d_out;
    float* outAsg   = outF;                         // assignment [4096]
    float* feat2    = outF + NB;                    // agg_n_2 = feat2 [4096,256]
    float* aggk2    = outF + NB + (size_t)NB * DD;  // agg_k_2 [1024,256]
    float* outLoss  = outF + NB + (size_t)NB * DD + (size_t)KK * DD;

    // encoders + norms
    k_gemm_nn<<<dim3(32, 2), TPB>>>(x1, W1, tmp, DIN, DD);
    k_rownorm<<<NB, TPB>>>(tmp, feat1);
    k_gemm_nn<<<dim3(32, 2), TPB>>>(x2, W2, tmp, DIN, DD);
    k_rownorm<<<NB, TPB>>>(tmp, feat2);
    k_rownorm<<<KK, TPB>>>(ctx1r, ctx1);
    k_rownorm<<<KK, TPB>>>(ctx2r, ctx2);
    k_rownorm<<<LL, TPB>>>(qn_r, qn);
    k_rownorm_queue<<<QKR, TPB>>>(qk_r, qnz, qkq);

    // view 1: logits, soft assign, hard argmax (output), agg_k_1
    k_gemm_nt<<<dim3(32, 8), TPB>>>(feat1, ctx1, logits, KK);
    k_softmax<<<NB, TPB>>>(logits, u1a, assign);
    k_argmax<<<NB, TPB>>>(logits, u1b, outAsg);
    k_colsum_part<<<dim3(KK / TPB, CSCH), TPB>>>(assign, csp);
    k_colsum_fin<<<KK / TPB, TPB>>>(csp, normk);
    k_gemm_tn_seg<<<dim3(8, 2, NSEG), TPB>>>(assign, feat1, aggp);
    k_aggk_finish<<<KK, TPB>>>(aggp, normk, aggk1);

    // view 2: logits, soft assign, agg_k_2 (output)
    k_gemm_nt<<<dim3(32, 8), TPB>>>(feat2, ctx2, logits, KK);
    k_softmax<<<NB, TPB>>>(logits, u2a, assign);
    k_colsum_part<<<dim3(KK / TPB, CSCH), TPB>>>(assign, csp);
    k_colsum_fin<<<KK / TPB, TPB>>>(csp, normk);
    k_gemm_tn_seg<<<dim3(8, 2, NSEG), TPB>>>(assign, feat2, aggp);
    k_aggk_finish<<<KK, TPB>>>(aggp, normk, aggk2);

    // loss_n : negatives vs queue_n (dominant GEMM, fused exp-sum)
    k_expsum<<<dim3(NB / 128, NCHN), TPB>>>(feat1, qn, partn, TPCN, NCHN);
    k_ce_row<<<NB, TPB>>>(feat1, feat2, partn, NCHN, lpn);

    // loss_k : negatives vs perturbed queue_k
    k_expsum<<<dim3(KK / 128, NCHK), TPB>>>(aggk1, qkq, partk, TPCK, NCHK);
    k_ce_row<<<KK, TPB>>>(aggk1, aggk2, partk, NCHK, lpk);

    k_loss<<<1, TPB>>>(lpn, lpk, outLoss);
}

// round 5
// speedup vs baseline: 1.9548x; 1.9548x over previous
#include <cuda_runtime.h>
#include <math.h>
#include <stdint.h>

#define TPB 256

// ---- problem sizes ----
constexpr int NB  = 4096;   // batch
constexpr int DIN = 1024;
constexpr int DD  = 256;
constexpr int KK  = 1024;   // clusters
constexpr int LL  = 32768;  // queue_n rows
constexpr int QKR = 4096;   // queue_k rows

constexpr int NSEG = 8;             // split-B segments for agg GEMM
constexpr int SEGB = NB / NSEG;     // 512
constexpr int NCHN = 16, TPCN = 16; // loss_n: 16 chunks x 16 tiles x 128 = 32768
constexpr int NCHK = 8,  TPCK = 4;  // loss_k:  8 chunks x  4 tiles x 128 = 4096
constexpr int CSCH = 32;            // colsum b-chunks

constexpr float INVT = 1.0f / 0.07f;

// dynamic smem layout for tensor-core expsum (uint32 words)
constexpr int AS_W   = 128 * 260;          // A tile tf32, padded stride 260
constexpr int BS_W   = 2 * 128 * 36;       // B double buffer, padded stride 36
constexpr int RED_W  = 128 * 4;            // per-row partials across 4 n-warps
constexpr int SMEM_TC = (AS_W + BS_W + RED_W) * 4;   // 172032 bytes

// ---- scratch offsets (floats) ----
constexpr size_t O_TMP    = 0;
constexpr size_t O_FEAT1  = O_TMP    + (size_t)NB*DD;
constexpr size_t O_CTX1   = O_FEAT1  + (size_t)NB*DD;
constexpr size_t O_CTX2   = O_CTX1   + (size_t)KK*DD;
constexpr size_t O_QN     = O_CTX2   + (size_t)KK*DD;
constexpr size_t O_QKQ    = O_QN     + (size_t)LL*DD;
constexpr size_t O_LOGITS = O_QKQ    + (size_t)QKR*DD;
constexpr size_t O_ASSIGN = O_LOGITS + (size_t)NB*KK;
constexpr size_t O_AGGK1  = O_ASSIGN + (size_t)NB*KK;
constexpr size_t O_AGGP   = O_AGGK1  + (size_t)KK*DD;
constexpr size_t O_CSP    = O_AGGP   + (size_t)NSEG*KK*DD;
constexpr size_t O_NORMK  = O_CSP    + (size_t)CSCH*KK;
constexpr size_t O_LPN    = O_NORMK  + KK;
constexpr size_t O_LPK    = O_LPN    + NB;
constexpr size_t O_PARTN  = O_LPK    + KK;
constexpr size_t O_PARTK  = O_PARTN  + (size_t)NB*NCHN;
constexpr size_t O_END    = O_PARTK  + (size_t)KK*NCHK;

__device__ float g_scratch[O_END];

// ---------------- helpers ----------------
__device__ __forceinline__ float gumbelf(float u) {
    u = u * (1.0f - 2e-6f) + 1e-6f;
    return -logf(-logf(u));
}

__device__ __forceinline__ uint32_t f2tf32(float x) {
    uint32_t u;
    asm("cvt.rna.tf32.f32 %0, %1;" : "=r"(u) : "f"(x));
    return u;
}

__device__ __forceinline__ void mma_tf32(
    float& c0, float& c1, float& c2, float& c3,
    uint32_t a0, uint32_t a1, uint32_t a2, uint32_t a3,
    uint32_t b0, uint32_t b1) {
    asm volatile(
        "mma.sync.aligned.m16n8k8.row.col.f32.tf32.tf32.f32 "
        "{%0,%1,%2,%3}, {%4,%5,%6,%7}, {%8,%9}, {%0,%1,%2,%3};\n"
        : "+f"(c0), "+f"(c1), "+f"(c2), "+f"(c3)
        : "r"(a0), "r"(a1), "r"(a2), "r"(a3), "r"(b0), "r"(b1));
}

__device__ __forceinline__ float blocksum256(float v) {
    __shared__ float sh_s[8];
    #pragma unroll
    for (int o = 16; o; o >>= 1) v += __shfl_xor_sync(0xffffffffu, v, o);
    if ((threadIdx.x & 31) == 0) sh_s[threadIdx.x >> 5] = v;
    __syncthreads();
    float s = 0.f;
    #pragma unroll
    for (int i = 0; i < 8; i++) s += sh_s[i];
    __syncthreads();
    return s;
}

__device__ __forceinline__ float blockmax256(float v) {
    __shared__ float sh_m[8];
    #pragma unroll
    for (int o = 16; o; o >>= 1) v = fmaxf(v, __shfl_xor_sync(0xffffffffu, v, o));
    if ((threadIdx.x & 31) == 0) sh_m[threadIdx.x >> 5] = v;
    __syncthreads();
    float s = sh_m[0];
    #pragma unroll
    for (int i = 1; i < 8; i++) s = fmaxf(s, sh_m[i]);
    __syncthreads();
    return s;
}

// ---------------- row L2 normalize (D = 256 = blockDim) ----------------
__global__ void k_rownorm(const float* __restrict__ src, float* __restrict__ dst) {
    int r = blockIdx.x, t = threadIdx.x;
    float v = src[(size_t)r * DD + t];
    float s = blocksum256(v * v);
    dst[(size_t)r * DD + t] = v * rsqrtf(fmaxf(s, 1e-12f));
}

// queue = l2norm(queue_k + qnoise + queue_k)
__global__ void k_rownorm_queue(const float* __restrict__ qk, const float* __restrict__ nz,
                                float* __restrict__ dst) {
    int r = blockIdx.x, t = threadIdx.x;
    size_t i = (size_t)r * DD + t;
    float v = (qk[i] + nz[i]) + qk[i];
    float s = blocksum256(v * v);
    dst[i] = v * rsqrtf(fmaxf(s, 1e-12f));
}

// ---------------- GEMM NN: C[M,N] = A[M,Kd] @ B[Kd,N] ----------------
__global__ void __launch_bounds__(TPB) k_gemm_nn(
    const float* __restrict__ A, const float* __restrict__ Bm,
    float* __restrict__ C, int Kd, int N) {
    __shared__ float As[16][132];
    __shared__ float Bs[16][132];
    const int tid = threadIdx.x;
    const int tx = tid & 15, ty = tid >> 4;
    const int m0 = blockIdx.x * 128, n0 = blockIdx.y * 128;
    float acc[8][8];
    #pragma unroll
    for (int i = 0; i < 8; i++)
        #pragma unroll
        for (int j = 0; j < 8; j++) acc[i][j] = 0.f;
    for (int k0 = 0; k0 < Kd; k0 += 16) {
        #pragma unroll
        for (int p = 0; p < 2; p++) {
            int i = tid + p * TPB;
            int r = i >> 2, v = i & 3;
            float4 q = *(const float4*)(A + (size_t)(m0 + r) * Kd + k0 + v * 4);
            As[v*4+0][r] = q.x; As[v*4+1][r] = q.y; As[v*4+2][r] = q.z; As[v*4+3][r] = q.w;
        }
        #pragma unroll
        for (int p = 0; p < 2; p++) {
            int i = tid + p * TPB;
            int kk = i >> 5, v = i & 31;
            *(float4*)(&Bs[kk][v*4]) = *(const float4*)(Bm + (size_t)(k0 + kk) * N + n0 + v * 4);
        }
        __syncthreads();
        #pragma unroll
        for (int kk = 0; kk < 16; kk++) {
            float a[8], b[8];
            *(float4*)(a)     = *(const float4*)(&As[kk][ty * 8]);
            *(float4*)(a + 4) = *(const float4*)(&As[kk][ty * 8 + 4]);
            *(float4*)(b)     = *(const float4*)(&Bs[kk][tx * 8]);
            *(float4*)(b + 4) = *(const float4*)(&Bs[kk][tx * 8 + 4]);
            #pragma unroll
            for (int i = 0; i < 8; i++)
                #pragma unroll
                for (int j = 0; j < 8; j++) acc[i][j] += a[i] * b[j];
        }
        __syncthreads();
    }
    #pragma unroll
    for (int i = 0; i < 8; i++) {
        float* cp = C + (size_t)(m0 + ty * 8 + i) * N + n0 + tx * 8;
        *(float4*)cp       = make_float4(acc[i][0], acc[i][1], acc[i][2], acc[i][3]);
        *(float4*)(cp + 4) = make_float4(acc[i][4], acc[i][5], acc[i][6], acc[i][7]);
    }
}

// ---------------- GEMM NT: C[M,N] = A[M,256] @ B[N,256]^T ----------------
__global__ void __launch_bounds__(TPB) k_gemm_nt(
    const float* __restrict__ A, const float* __restrict__ Bm,
    float* __restrict__ C, int N) {
    __shared__ float As[16][132];
    __shared__ float Bs[16][132];
    const int tid = threadIdx.x;
    const int tx = tid & 15, ty = tid >> 4;
    const int m0 = blockIdx.x * 128, n0 = blockIdx.y * 128;
    float acc[8][8];
    #pragma unroll
    for (int i = 0; i < 8; i++)
        #pragma unroll
        for (int j = 0; j < 8; j++) acc[i][j] = 0.f;
    for (int k0 = 0; k0 < DD; k0 += 16) {
        #pragma unroll
        for (int p = 0; p < 2; p++) {
            int i = tid + p * TPB;
            int r = i >> 2, v = i & 3;
            float4 q = *(const float4*)(A + (size_t)(m0 + r) * DD + k0 + v * 4);
            As[v*4+0][r] = q.x; As[v*4+1][r] = q.y; As[v*4+2][r] = q.z; As[v*4+3][r] = q.w;
        }
        #pragma unroll
        for (int p = 0; p < 2; p++) {
            int i = tid + p * TPB;
            int n = i >> 2, v = i & 3;
            float4 q = *(const float4*)(Bm + (size_t)(n0 + n) * DD + k0 + v * 4);
            Bs[v*4+0][n] = q.x; Bs[v*4+1][n] = q.y; Bs[v*4+2][n] = q.z; Bs[v*4+3][n] = q.w;
        }
        __syncthreads();
        #pragma unroll
        for (int kk = 0; kk < 16; kk++) {
            float a[8], b[8];
            *(float4*)(a)     = *(const float4*)(&As[kk][ty * 8]);
            *(float4*)(a + 4) = *(const float4*)(&As[kk][ty * 8 + 4]);
            *(float4*)(b)     = *(const float4*)(&Bs[kk][tx * 8]);
            *(float4*)(b + 4) = *(const float4*)(&Bs[kk][tx * 8 + 4]);
            #pragma unroll
            for (int i = 0; i < 8; i++)
                #pragma unroll
                for (int j = 0; j < 8; j++) acc[i][j] += a[i] * b[j];
        }
        __syncthreads();
    }
    #pragma unroll
    for (int i = 0; i < 8; i++) {
        float* cp = C + (size_t)(m0 + ty * 8 + i) * N + n0 + tx * 8;
        *(float4*)cp       = make_float4(acc[i][0], acc[i][1], acc[i][2], acc[i][3]);
        *(float4*)(cp + 4) = make_float4(acc[i][4], acc[i][5], acc[i][6], acc[i][7]);
    }
}

// -------- GEMM TN split-B: Cpart[z] = assign[seg z]^T @ feat ----------
__global__ void __launch_bounds__(TPB) k_gemm_tn_seg(
    const float* __restrict__ Asg, const float* __restrict__ Fm,
    float* __restrict__ Cpart) {
    __shared__ float As[16][132];
    __shared__ float Bs[16][132];
    const int tid = threadIdx.x;
    const int tx = tid & 15, ty = tid >> 4;
    const int m0 = blockIdx.x * 128;   // cluster dim
    const int n0 = blockIdx.y * 128;   // feature dim
    const int z  = blockIdx.z;
    float acc[8][8];
    #pragma unroll
    for (int i = 0; i < 8; i++)
        #pragma unroll
        for (int j = 0; j < 8; j++) acc[i][j] = 0.f;
    for (int b0 = z * SEGB; b0 < (z + 1) * SEGB; b0 += 16) {
        #pragma unroll
        for (int p = 0; p < 2; p++) {
            int i = tid + p * TPB;
            int bb = i >> 5, v = i & 31;
            *(float4*)(&As[bb][v*4]) = *(const float4*)(Asg + (size_t)(b0 + bb) * KK + m0 + v * 4);
        }
        #pragma unroll
        for (int p = 0; p < 2; p++) {
            int i = tid + p * TPB;
            int bb = i >> 5, v = i & 31;
            *(float4*)(&Bs[bb][v*4]) = *(const float4*)(Fm + (size_t)(b0 + bb) * DD + n0 + v * 4);
        }
        __syncthreads();
        #pragma unroll
        for (int bb = 0; bb < 16; bb++) {
            float a[8], b[8];
            *(float4*)(a)     = *(const float4*)(&As[bb][ty * 8]);
            *(float4*)(a + 4) = *(const float4*)(&As[bb][ty * 8 + 4]);
            *(float4*)(b)     = *(const float4*)(&Bs[bb][tx * 8]);
            *(float4*)(b + 4) = *(const float4*)(&Bs[bb][tx * 8 + 4]);
            #pragma unroll
            for (int i = 0; i < 8; i++)
                #pragma unroll
                for (int j = 0; j < 8; j++) acc[i][j] += a[i] * b[j];
        }
        __syncthreads();
    }
    #pragma unroll
    for (int i = 0; i < 8; i++) {
        float* cp = Cpart + (size_t)z * KK * DD + (size_t)(m0 + ty * 8 + i) * DD + n0 + tx * 8;
        *(float4*)cp       = make_float4(acc[i][0], acc[i][1], acc[i][2], acc[i][3]);
        *(float4*)(cp + 4) = make_float4(acc[i][4], acc[i][5], acc[i][6], acc[i][7]);
    }
}

// ======== tensor-core tf32 negatives GEMM + fused streaming exp-sum ========
// Block: 256 thr = 8 warps (2 m-groups x 4 n-groups). Tile: 128 A-rows.
// A tile tf32 resident in smem; B k-chunks (32) double-buffered w/ reg prefetch.
__global__ void __launch_bounds__(TPB) k_expsum_tc(
    const float* __restrict__ Am, const float* __restrict__ Qm,
    float* __restrict__ part, int tpc, int nch) {
    extern __shared__ uint32_t dsm[];
    uint32_t* AsU = dsm;               // [128][260]
    uint32_t* BsU = dsm + AS_W;        // [2][128][36]
    float*    red = (float*)(dsm + AS_W + BS_W);  // [128][4]

    const int tid  = threadIdx.x;
    const int lane = tid & 31;
    const int wid  = tid >> 5;
    const int g    = lane >> 2, tg = lane & 3;
    const int wm   = wid >> 2,  wn = wid & 3;
    const int m0w  = wm * 64,   n0w = wn * 32;
    const int m0   = blockIdx.x * 128;
    const int chunk = blockIdx.y;

    // Load A [128 x 256] fp32 -> tf32 smem
    #pragma unroll 8
    for (int it = 0; it < 32; it++) {
        int idx = it * TPB + tid;
        int r = idx >> 6, c4 = idx & 63;
        float4 q = *(const float4*)(Am + (size_t)(m0 + r) * DD + c4 * 4);
        uint32_t* p = AsU + r * 260 + c4 * 4;
        p[0] = f2tf32(q.x); p[1] = f2tf32(q.y); p[2] = f2tf32(q.z); p[3] = f2tf32(q.w);
    }

    int rA0[4], rA1[4], rB[4];
    #pragma unroll
    for (int i = 0; i < 4; i++) { rA0[i] = (m0w + i*16 + g) * 260; rA1[i] = rA0[i] + 8*260; }
    #pragma unroll
    for (int j = 0; j < 4; j++) rB[j] = (n0w + j*8 + g) * 36;

    float rp[4][2];
    #pragma unroll
    for (int i = 0; i < 4; i++) { rp[i][0] = 0.f; rp[i][1] = 0.f; }

    int buf = 0;
    __syncthreads();   // A visible

    for (int t = 0; t < tpc; t++) {
        const int n0 = (chunk * tpc + t) * 128;

        __syncthreads();  // prior tile's reads of Bs[buf] complete
        #pragma unroll
        for (int it = 0; it < 4; it++) {
            int idx = it * TPB + tid;
            int r = idx >> 3, c4 = idx & 7;
            float4 q = *(const float4*)(Qm + (size_t)(n0 + r) * DD + c4 * 4);
            uint32_t* p = BsU + buf * 4608 + r * 36 + c4 * 4;
            p[0] = f2tf32(q.x); p[1] = f2tf32(q.y); p[2] = f2tf32(q.z); p[3] = f2tf32(q.w);
        }
        __syncthreads();

        float acc[4][4][4];
        #pragma unroll
        for (int i = 0; i < 4; i++)
            #pragma unroll
            for (int j = 0; j < 4; j++)
                #pragma unroll
                for (int c = 0; c < 4; c++) acc[i][j][c] = 0.f;

        for (int kc = 0; kc < 8; kc++) {
            float4 pre[4];
            if (kc < 7) {
                int k0n = (kc + 1) * 32;
                #pragma unroll
                for (int it = 0; it < 4; it++) {
                    int idx = it * TPB + tid;
                    int r = idx >> 3, c4 = idx & 7;
                    pre[it] = *(const float4*)(Qm + (size_t)(n0 + r) * DD + k0n + c4 * 4);
                }
            }
            const uint32_t* bsb = BsU + buf * 4608;
            #pragma unroll
            for (int ks = 0; ks < 4; ks++) {
                int k = kc * 32 + ks * 8;
                uint32_t a[4][4];
                #pragma unroll
                for (int i = 0; i < 4; i++) {
                    a[i][0] = AsU[rA0[i] + k + tg];
                    a[i][1] = AsU[rA1[i] + k + tg];
                    a[i][2] = AsU[rA0[i] + k + 4 + tg];
                    a[i][3] = AsU[rA1[i] + k + 4 + tg];
                }
                int kl = ks * 8 + tg;
                #pragma unroll
                for (int j = 0; j < 4; j++) {
                    uint32_t b0 = bsb[rB[j] + kl], b1 = bsb[rB[j] + kl + 4];
                    #pragma unroll
                    for (int i = 0; i < 4; i++)
                        mma_tf32(acc[i][j][0], acc[i][j][1], acc[i][j][2], acc[i][j][3],
                                 a[i][0], a[i][1], a[i][2], a[i][3], b0, b1);
                }
            }
            if (kc < 7) {
                #pragma unroll
                for (int it = 0; it < 4; it++) {
                    int idx = it * TPB + tid;
                    int r = idx >> 3, c4 = idx & 7;
                    uint32_t* p = BsU + (buf ^ 1) * 4608 + r * 36 + c4 * 4;
                    p[0] = f2tf32(pre[it].x); p[1] = f2tf32(pre[it].y);
                    p[2] = f2tf32(pre[it].z); p[3] = f2tf32(pre[it].w);
                }
                __syncthreads();
                buf ^= 1;
            }
        }

        // fused exp-sum epilogue: c0/c1 belong to row g, c2/c3 to row g+8;
        // columns are all summed anyway so their ids are irrelevant.
        #pragma unroll
        for (int i = 0; i < 4; i++) {
            float s0 = 0.f, s1 = 0.f;
            #pragma unroll
            for (int j = 0; j < 4; j++) {
                s0 += __expf(acc[i][j][0] * INVT - INVT) + __expf(acc[i][j][1] * INVT - INVT);
                s1 += __expf(acc[i][j][2] * INVT - INVT) + __expf(acc[i][j][3] * INVT - INVT);
            }
            rp[i][0] += s0; rp[i][1] += s1;
        }
    }

    // reduce the 4 lanes sharing each row, then across the 4 n-group warps
    #pragma unroll
    for (int i = 0; i < 4; i++)
        #pragma unroll
        for (int h = 0; h < 2; h++) {
            float v = rp[i][h];
            v += __shfl_xor_sync(0xffffffffu, v, 1);
            v += __shfl_xor_sync(0xffffffffu, v, 2);
            if (tg == 0) red[(m0w + i*16 + h*8 + g) * 4 + wn] = v;
        }
    __syncthreads();
    if (tid < 128) {
        float s = red[tid*4+0] + red[tid*4+1] + red[tid*4+2] + red[tid*4+3];
        part[(size_t)(m0 + tid) * nch + chunk] = s;
    }
}

// ---------------- gumbel softmax (soft) over K=1024 ----------------
__global__ void k_softmax(const float* __restrict__ logits, const float* __restrict__ u,
                          float* __restrict__ assign) {
    int r = blockIdx.x, t = threadIdx.x;
    float z[4];
    #pragma unroll
    for (int j = 0; j < 4; j++) {
        int k = j * 256 + t;
        size_t i = (size_t)r * KK + k;
        z[j] = (logits[i] + gumbelf(u[i])) * 2.0f;   // 1/GUMBEL_TEMP
    }
    float m = fmaxf(fmaxf(z[0], z[1]), fmaxf(z[2], z[3]));
    m = blockmax256(m);
    float s = 0.f;
    #pragma unroll
    for (int j = 0; j < 4; j++) { z[j] = __expf(z[j] - m); s += z[j]; }
    s = blocksum256(s);
    float inv = 1.0f / s;
    #pragma unroll
    for (int j = 0; j < 4; j++) {
        int k = j * 256 + t;
        assign[(size_t)r * KK + k] = z[j] * inv;
    }
}

// ---------------- hard-path argmax(logits + gumbel), first-index ties ----
__global__ void k_argmax(const float* __restrict__ logits, const float* __restrict__ u,
                         float* __restrict__ out) {
    __shared__ float sb[8]; __shared__ int si[8];
    int r = blockIdx.x, t = threadIdx.x;
    float best = -1e30f; int bi = 0;
    #pragma unroll
    for (int j = 0; j < 4; j++) {
        int k = j * 256 + t;
        size_t i = (size_t)r * KK + k;
        float z = logits[i] + gumbelf(u[i]);
        if (z > best) { best = z; bi = k; }
    }
    #pragma unroll
    for (int o = 16; o; o >>= 1) {
        float ob = __shfl_xor_sync(0xffffffffu, best, o);
        int   oi = __shfl_xor_sync(0xffffffffu, bi, o);
        if (ob > best || (ob == best && oi < bi)) { best = ob; bi = oi; }
    }
    if ((t & 31) == 0) { sb[t >> 5] = best; si[t >> 5] = bi; }
    __syncthreads();
    if (t == 0) {
        #pragma unroll
        for (int w = 1; w < 8; w++)
            if (sb[w] > best || (sb[w] == best && si[w] < bi)) { best = sb[w]; bi = si[w]; }
        out[r] = (float)bi;
    }
}

// ---------------- column sums of assign (normalizer) ----------------
__global__ void k_colsum_part(const float* __restrict__ assign, float* __restrict__ csp) {
    int k = blockIdx.x * TPB + threadIdx.x;
    int c = blockIdx.y;
    float s = 0.f;
    #pragma unroll 4
    for (int b = c * (NB / CSCH); b < (c + 1) * (NB / CSCH); b++)
        s += assign[(size_t)b * KK + k];
    csp[(size_t)c * KK + k] = s;
}
__global__ void k_colsum_fin(const float* __restrict__ csp, float* __restrict__ norm) {
    int k = blockIdx.x * TPB + threadIdx.x;
    float s = 0.f;
    #pragma unroll
    for (int c = 0; c < CSCH; c++) s += csp[(size_t)c * KK + k];
    norm[k] = s;
}

// ---------------- agg_k finish: sum partials, /norm, L2 normalize ----------
__global__ void k_aggk_finish(const float* __restrict__ part, const float* __restrict__ norm,
                              float* __restrict__ dst) {
    int r = blockIdx.x, t = threadIdx.x;
    float v = 0.f;
    #pragma unroll
    for (int s = 0; s < NSEG; s++) v += part[(size_t)s * KK * DD + (size_t)r * DD + t];
    v = v / (norm[r] + 1e-8f);
    float ss = blocksum256(v * v);
    dst[(size_t)r * DD + t] = v * rsqrtf(fmaxf(ss, 1e-12f));
}

// ------------- per-row CE: lp = lpos/T - logsumexp (shifted) -------------
__global__ void k_ce_row(const float* __restrict__ q, const float* __restrict__ kv,
                         const float* __restrict__ part, int nch,
                         float* __restrict__ lp) {
    int r = blockIdx.x, t = threadIdx.x;
    float v = q[(size_t)r * DD + t] * kv[(size_t)r * DD + t];
    float lpos = blocksum256(v);
    if (t == 0) {
        float S = expf(lpos * INVT - INVT);
        for (int c = 0; c < nch; c++) S += part[(size_t)r * nch + c];
        lp[r] = lpos * INVT - INVT - logf(S);
    }
}

// ---------------- final scalar loss ----------------
__global__ void k_loss(const float* __restrict__ lpn, const float* __restrict__ lpk,
                       float* __restrict__ out) {
    int t = threadIdx.x;
    float s1 = 0.f;
    for (int i = t; i < NB; i += TPB) s1 += lpn[i];
    s1 = blocksum256(s1);
    float s2 = 0.f;
    for (int i = t; i < KK; i += TPB) s2 += lpk[i];
    s2 = blocksum256(s2);
    if (t == 0) out[0] = -(s1 / NB) - (s2 / KK);
}

// ============================ launcher ============================
extern "C" void kernel_launch(void* const* d_in, const int* in_sizes, int n_in,
                              void* d_out, int out_size) {
    const float* x1    = (const float*)d_in[0];
    const float* x2    = (const float*)d_in[1];
    const float* W1    = (const float*)d_in[2];
    const float* W2    = (const float*)d_in[3];
    const float* ctx1r = (const float*)d_in[4];
    const float* ctx2r = (const float*)d_in[5];
    const float* qn_r  = (const float*)d_in[6];
    const float* qk_r  = (const float*)d_in[7];
    const float* u1a   = (const float*)d_in[8];
    const float* u1b   = (const float*)d_in[9];
    const float* u2a   = (const float*)d_in[10];
    const float* u2b   = (const float*)d_in[11];
    const float* qnz   = (const float*)d_in[12];
    (void)u2b; (void)in_sizes; (void)n_in; (void)out_size;

    cudaFuncSetAttribute(k_expsum_tc, cudaFuncAttributeMaxDynamicSharedMemorySize, SMEM_TC);

    float* S;
    cudaGetSymbolAddress((void**)&S, g_scratch);
    float* tmp    = S + O_TMP;
    float* feat1  = S + O_FEAT1;
    float* ctx1   = S + O_CTX1;
    float* ctx2   = S + O_CTX2;
    float* qn     = S + O_QN;
    float* qkq    = S + O_QKQ;
    float* logits = S + O_LOGITS;
    float* assign = S + O_ASSIGN;
    float* aggk1  = S + O_AGGK1;
    float* aggp   = S + O_AGGP;
    float* csp    = S + O_CSP;
    float* normk  = S + O_NORMK;
    float* lpn    = S + O_LPN;
    float* lpk    = S + O_LPK;
    float* partn  = S + O_PARTN;
    float* partk  = S + O_PARTK;

    float* outF     = (float*)d_out;
    float* outAsg   = outF;                         // assignment [4096]
    float* feat2    = outF + NB;                    // agg_n_2 = feat2 [4096,256]
    float* aggk2    = outF + NB + (size_t)NB * DD;  // agg_k_2 [1024,256]
    float* outLoss  = outF + NB + (size_t)NB * DD + (size_t)KK * DD;

    // encoders + norms
    k_gemm_nn<<<dim3(32, 2), TPB>>>(x1, W1, tmp, DIN, DD);
    k_rownorm<<<NB, TPB>>>(tmp, feat1);
    k_gemm_nn<<<dim3(32, 2), TPB>>>(x2, W2, tmp, DIN, DD);
    k_rownorm<<<NB, TPB>>>(tmp, feat2);
    k_rownorm<<<KK, TPB>>>(ctx1r, ctx1);
    k_rownorm<<<KK, TPB>>>(ctx2r, ctx2);
    k_rownorm<<<LL, TPB>>>(qn_r, qn);
    k_rownorm_queue<<<QKR, TPB>>>(qk_r, qnz, qkq);

    // view 1: logits, soft assign, hard argmax (output), agg_k_1
    k_gemm_nt<<<dim3(32, 8), TPB>>>(feat1, ctx1, logits, KK);
    k_softmax<<<NB, TPB>>>(logits, u1a, assign);
    k_argmax<<<NB, TPB>>>(logits, u1b, outAsg);
    k_colsum_part<<<dim3(KK / TPB, CSCH), TPB>>>(assign, csp);
    k_colsum_fin<<<KK / TPB, TPB>>>(csp, normk);
    k_gemm_tn_seg<<<dim3(8, 2, NSEG), TPB>>>(assign, feat1, aggp);
    k_aggk_finish<<<KK, TPB>>>(aggp, normk, aggk1);

    // view 2: logits, soft assign, agg_k_2 (output)
    k_gemm_nt<<<dim3(32, 8), TPB>>>(feat2, ctx2, logits, KK);
    k_softmax<<<NB, TPB>>>(logits, u2a, assign);
    k_colsum_part<<<dim3(KK / TPB, CSCH), TPB>>>(assign, csp);
    k_colsum_fin<<<KK / TPB, TPB>>>(csp, normk);
    k_gemm_tn_seg<<<dim3(8, 2, NSEG), TPB>>>(assign, feat2, aggp);
    k_aggk_finish<<<KK, TPB>>>(aggp, normk, aggk2);

    // loss_n : negatives vs queue_n (tensor-core tf32, fused exp-sum)
    k_expsum_tc<<<dim3(NB / 128, NCHN), TPB, SMEM_TC>>>(feat1, qn, partn, TPCN, NCHN);
    k_ce_row<<<NB, TPB>>>(feat1, feat2, partn, NCHN, lpn);

    // loss_k : negatives vs perturbed queue_k (tensor-core tf32)
    k_expsum_tc<<<dim3(KK / 128, NCHK), TPB, SMEM_TC>>>(aggk1, qkq, partk, TPCK, NCHK);
    k_ce_row<<<KK, TPB>>>(aggk1, aggk2, partk, NCHK, lpk);

    k_loss<<<1, TPB>>>(lpn, lpk, outLoss);
}

// round 8
// speedup vs baseline: 2.2627x; 1.1575x over previous
#include <cuda_runtime.h>
#include <math.h>
#include <stdint.h>

#define TPB 256

// ---- problem sizes ----
constexpr int NB  = 4096;   // batch
constexpr int DIN = 1024;
constexpr int DD  = 256;
constexpr int KK  = 1024;   // clusters
constexpr int LL  = 32768;  // queue_n rows
constexpr int QKR = 4096;   // queue_k rows

constexpr int NSEG = 8;             // split-B segments for agg GEMM
constexpr int SEGB = NB / NSEG;     // 512
constexpr int NCHN = 16, TPCN = 16; // loss_n chunks/tiles
constexpr int NCHK = 8,  TPCK = 4;  // loss_k chunks/tiles
constexpr int CSCH = 32;            // colsum b-chunks

constexpr float INVT = 1.0f / 0.07f;

// expsum smem (uint32 words)
constexpr int AS_W   = 128 * 260;
constexpr int BS_W   = 2 * 128 * 36;
constexpr int RED_W  = 128 * 4;
constexpr int SMEM_TC = (AS_W + BS_W + RED_W) * 4;   // 172032 B

// nt3 smem: 2 bufs x (AH, AL, BH, BL) each 128x36 words
constexpr int G_CH = 128 * 36;
constexpr int SMEM_NT3 = 2 * 4 * G_CH * 4;           // 147456 B

// ---- scratch offsets (floats) ----
constexpr size_t O_TMP    = 0;
constexpr size_t O_FEAT1  = O_TMP    + (size_t)NB*DD;
constexpr size_t O_CTX1   = O_FEAT1  + (size_t)NB*DD;
constexpr size_t O_CTX2   = O_CTX1   + (size_t)KK*DD;
constexpr size_t O_QN     = O_CTX2   + (size_t)KK*DD;
constexpr size_t O_QKQ    = O_QN     + (size_t)LL*DD;
constexpr size_t O_LOGITS = O_QKQ    + (size_t)QKR*DD;
constexpr size_t O_ASSIGN = O_LOGITS + (size_t)NB*KK;
constexpr size_t O_AGGK1  = O_ASSIGN + (size_t)NB*KK;
constexpr size_t O_AGGP   = O_AGGK1  + (size_t)KK*DD;
constexpr size_t O_CSP    = O_AGGP   + (size_t)NSEG*KK*DD;
constexpr size_t O_NORMK  = O_CSP    + (size_t)CSCH*KK;
constexpr size_t O_LPN    = O_NORMK  + KK;
constexpr size_t O_LPK    = O_LPN    + NB;
constexpr size_t O_PARTN  = O_LPK    + KK;
constexpr size_t O_PARTK  = O_PARTN  + (size_t)NB*NCHN;
constexpr size_t O_W1T    = O_PARTK  + (size_t)KK*NCHK;
constexpr size_t O_W2T    = O_W1T    + (size_t)DD*DIN;
constexpr size_t O_END    = O_W2T    + (size_t)DD*DIN;

__device__ float g_scratch[O_END];

// ---------------- helpers ----------------
__device__ __forceinline__ float gumbelf(float u) {         // accurate (argmax path)
    u = u * (1.0f - 2e-6f) + 1e-6f;
    return -logf(-logf(u));
}
__device__ __forceinline__ float gumbelf_soft(float u) {    // soft path: fast outer log
    u = u * (1.0f - 2e-6f) + 1e-6f;
    return -__logf(-logf(u));
}

__device__ __forceinline__ uint32_t f2tf32(float x) {
    uint32_t u;
    asm("cvt.rna.tf32.f32 %0, %1;" : "=r"(u) : "f"(x));
    return u;
}

__device__ __forceinline__ void mma_tf32(
    float& c0, float& c1, float& c2, float& c3,
    uint32_t a0, uint32_t a1, uint32_t a2, uint32_t a3,
    uint32_t b0, uint32_t b1) {
    asm volatile(
        "mma.sync.aligned.m16n8k8.row.col.f32.tf32.tf32.f32 "
        "{%0,%1,%2,%3}, {%4,%5,%6,%7}, {%8,%9}, {%0,%1,%2,%3};\n"
        : "+f"(c0), "+f"(c1), "+f"(c2), "+f"(c3)
        : "r"(a0), "r"(a1), "r"(a2), "r"(a3), "r"(b0), "r"(b1));
}

__device__ __forceinline__ float blocksum256(float v) {
    __shared__ float sh_s[8];
    #pragma unroll
    for (int o = 16; o; o >>= 1) v += __shfl_xor_sync(0xffffffffu, v, o);
    if ((threadIdx.x & 31) == 0) sh_s[threadIdx.x >> 5] = v;
    __syncthreads();
    float s = 0.f;
    #pragma unroll
    for (int i = 0; i < 8; i++) s += sh_s[i];
    __syncthreads();
    return s;
}

__device__ __forceinline__ float blockmax256(float v) {
    __shared__ float sh_m[8];
    #pragma unroll
    for (int o = 16; o; o >>= 1) v = fmaxf(v, __shfl_xor_sync(0xffffffffu, v, o));
    if ((threadIdx.x & 31) == 0) sh_m[threadIdx.x >> 5] = v;
    __syncthreads();
    float s = sh_m[0];
    #pragma unroll
    for (int i = 1; i < 8; i++) s = fmaxf(s, sh_m[i]);
    __syncthreads();
    return s;
}

// ---------- warp-per-row L2 normalize (8 rows/block, float4) ----------
__global__ void k_rownorm_w(const float* __restrict__ src, float* __restrict__ dst) {
    int wid = threadIdx.x >> 5, lane = threadIdx.x & 31;
    int row = blockIdx.x * 8 + wid;
    const float4* s = (const float4*)(src + (size_t)row * DD);
    float4 a = s[lane], b = s[lane + 32];
    float ss = a.x*a.x + a.y*a.y + a.z*a.z + a.w*a.w
             + b.x*b.x + b.y*b.y + b.z*b.z + b.w*b.w;
    #pragma unroll
    for (int o = 16; o; o >>= 1) ss += __shfl_xor_sync(0xffffffffu, ss, o);
    float r = rsqrtf(fmaxf(ss, 1e-12f));
    float4* d = (float4*)(dst + (size_t)row * DD);
    d[lane]      = make_float4(a.x*r, a.y*r, a.z*r, a.w*r);
    d[lane + 32] = make_float4(b.x*r, b.y*r, b.z*r, b.w*r);
}

// queue = l2norm(2*queue_k + qnoise), warp-per-row
__global__ void k_rownorm_queue_w(const float* __restrict__ qk, const float* __restrict__ nz,
                                  float* __restrict__ dst) {
    int wid = threadIdx.x >> 5, lane = threadIdx.x & 31;
    int row = blockIdx.x * 8 + wid;
    const float4* q = (const float4*)(qk + (size_t)row * DD);
    const float4* n = (const float4*)(nz + (size_t)row * DD);
    float4 qa = q[lane], qb = q[lane + 32];
    float4 na = n[lane], nb = n[lane + 32];
    float4 a = make_float4(qa.x+na.x+qa.x, qa.y+na.y+qa.y, qa.z+na.z+qa.z, qa.w+na.w+qa.w);
    float4 b = make_float4(qb.x+nb.x+qb.x, qb.y+nb.y+qb.y, qb.z+nb.z+qb.z, qb.w+nb.w+qb.w);
    float ss = a.x*a.x + a.y*a.y + a.z*a.z + a.w*a.w
             + b.x*b.x + b.y*b.y + b.z*b.z + b.w*b.w;
    #pragma unroll
    for (int o = 16; o; o >>= 1) ss += __shfl_xor_sync(0xffffffffu, ss, o);
    float r = rsqrtf(fmaxf(ss, 1e-12f));
    float4* d = (float4*)(dst + (size_t)row * DD);
    d[lane]      = make_float4(a.x*r, a.y*r, a.z*r, a.w*r);
    d[lane + 32] = make_float4(b.x*r, b.y*r, b.z*r, b.w*r);
}

// ---------------- 32x32 tiled transpose: dst[C,R] = src[R,C]^T -------------
__global__ void k_transpose(const float* __restrict__ src, float* __restrict__ dst,
                            int R, int C) {
    __shared__ float t[32][33];
    int bx = blockIdx.x * 32, by = blockIdx.y * 32;
    int tx = threadIdx.x, ty = threadIdx.y;
    #pragma unroll
    for (int i = 0; i < 4; i++)
        t[ty + i*8][tx] = src[(size_t)(by + ty + i*8) * C + bx + tx];
    __syncthreads();
    #pragma unroll
    for (int i = 0; i < 4; i++)
        dst[(size_t)(bx + ty + i*8) * R + by + tx] = t[tx][ty + i*8];
}

// ======= 3xTF32 tensor-core GEMM NT: C[M,N] = A[M,K] @ B[N,K]^T =======
// Block 256 thr = 8 warps (2 m x 4 n). C tile 128x128. k-chunk 32, double buffer.
__global__ void __launch_bounds__(TPB) k_gemm_nt3(
    const float* __restrict__ A, const float* __restrict__ B,
    float* __restrict__ C, int K, int N) {
    extern __shared__ uint32_t sm3[];
    const int tid  = threadIdx.x;
    const int lane = tid & 31;
    const int wid  = tid >> 5;
    const int g    = lane >> 2, tg = lane & 3;
    const int wm   = wid >> 2,  wn = wid & 3;
    const int m0w  = wm * 64,   n0w = wn * 32;
    const int m0   = blockIdx.x * 128, n0 = blockIdx.y * 128;
    const int KC   = K >> 5;

    float acc[4][4][4];
    #pragma unroll
    for (int i = 0; i < 4; i++)
        #pragma unroll
        for (int j = 0; j < 4; j++)
            #pragma unroll
            for (int c = 0; c < 4; c++) acc[i][j][c] = 0.f;

    // chunk 0 load: A and B 128x32 each, split hi/lo
    #pragma unroll
    for (int it = 0; it < 4; it++) {
        int idx = it * TPB + tid;
        int r = idx >> 3, c4 = idx & 7;
        float4 qa = *(const float4*)(A + (size_t)(m0 + r) * K + c4 * 4);
        float4 qb = *(const float4*)(B + (size_t)(n0 + r) * K + c4 * 4);
        uint32_t* pah = sm3 + r * 36 + c4 * 4;
        uint32_t* pal = pah + G_CH;
        uint32_t* pbh = pah + 2 * G_CH;
        uint32_t* pbl = pah + 3 * G_CH;
        float va[4] = {qa.x, qa.y, qa.z, qa.w};
        float vb[4] = {qb.x, qb.y, qb.z, qb.w};
        #pragma unroll
        for (int c = 0; c < 4; c++) {
            uint32_t h = f2tf32(va[c]);
            pah[c] = h; pal[c] = f2tf32(va[c] - __uint_as_float(h));
            uint32_t hb = f2tf32(vb[c]);
            pbh[c] = hb; pbl[c] = f2tf32(vb[c] - __uint_as_float(hb));
        }
    }
    __syncthreads();

    int buf = 0;
    for (int kc = 0; kc < KC; kc++) {
        float4 pa[4], pb[4];
        if (kc < KC - 1) {
            int k0n = (kc + 1) * 32;
            #pragma unroll
            for (int it = 0; it < 4; it++) {
                int idx = it * TPB + tid;
                int r = idx >> 3, c4 = idx & 7;
                pa[it] = *(const float4*)(A + (size_t)(m0 + r) * K + k0n + c4 * 4);
                pb[it] = *(const float4*)(B + (size_t)(n0 + r) * K + k0n + c4 * 4);
            }
        }
        const uint32_t* AH = sm3 + buf * 4 * G_CH;
        const uint32_t* AL = AH + G_CH;
        const uint32_t* BH = AH + 2 * G_CH;
        const uint32_t* BL = AH + 3 * G_CH;
        #pragma unroll
        for (int ks = 0; ks < 4; ks++) {
            int kk = ks * 8 + tg;
            uint32_t ah[4][4], al[4][4];
            #pragma unroll
            for (int i = 0; i < 4; i++) {
                int base = (m0w + i * 16 + g) * 36;
                ah[i][0] = AH[base + kk];          ah[i][1] = AH[base + 8*36 + kk];
                ah[i][2] = AH[base + kk + 4];      ah[i][3] = AH[base + 8*36 + kk + 4];
                al[i][0] = AL[base + kk];          al[i][1] = AL[base + 8*36 + kk];
                al[i][2] = AL[base + kk + 4];      al[i][3] = AL[base + 8*36 + kk + 4];
            }
            #pragma unroll
            for (int j = 0; j < 4; j++) {
                int bbase = (n0w + j * 8 + g) * 36;
                uint32_t bh0 = BH[bbase + kk], bh1 = BH[bbase + kk + 4];
                uint32_t bl0 = BL[bbase + kk], bl1 = BL[bbase + kk + 4];
                #pragma unroll
                for (int i = 0; i < 4; i++) {
                    mma_tf32(acc[i][j][0], acc[i][j][1], acc[i][j][2], acc[i][j][3],
                             ah[i][0], ah[i][1], ah[i][2], ah[i][3], bh0, bh1);
                    mma_tf32(acc[i][j][0], acc[i][j][1], acc[i][j][2], acc[i][j][3],
                             ah[i][0], ah[i][1], ah[i][2], ah[i][3], bl0, bl1);
                    mma_tf32(acc[i][j][0], acc[i][j][1], acc[i][j][2], acc[i][j][3],
                             al[i][0], al[i][1], al[i][2], al[i][3], bh0, bh1);
                }
            }
        }
        if (kc < KC - 1) {
            uint32_t* dst = sm3 + (buf ^ 1) * 4 * G_CH;
            #pragma unroll
            for (int it = 0; it < 4; it++) {
                int idx = it * TPB + tid;
                int r = idx >> 3, c4 = idx & 7;
                uint32_t* pah = dst + r * 36 + c4 * 4;
                uint32_t* pal = pah + G_CH;
                uint32_t* pbh = pah + 2 * G_CH;
                uint32_t* pbl = pah + 3 * G_CH;
                float va[4] = {pa[it].x, pa[it].y, pa[it].z, pa[it].w};
                float vb[4] = {pb[it].x, pb[it].y, pb[it].z, pb[it].w};
                #pragma unroll
                for (int c = 0; c < 4; c++) {
                    uint32_t h = f2tf32(va[c]);
                    pah[c] = h; pal[c] = f2tf32(va[c] - __uint_as_float(h));
                    uint32_t hb = f2tf32(vb[c]);
                    pbh[c] = hb; pbl[c] = f2tf32(vb[c] - __uint_as_float(hb));
                }
            }
            __syncthreads();
            buf ^= 1;
        }
    }

    // epilogue: c0,c1 -> (row g, cols 2tg,2tg+1); c2,c3 -> row g+8
    #pragma unroll
    for (int i = 0; i < 4; i++) {
        int row = m0 + m0w + i * 16 + g;
        #pragma unroll
        for (int j = 0; j < 4; j++) {
            int col = n0 + n0w + j * 8 + tg * 2;
            *(float2*)(C + (size_t)row * N + col)       = make_float2(acc[i][j][0], acc[i][j][1]);
            *(float2*)(C + (size_t)(row + 8) * N + col) = make_float2(acc[i][j][2], acc[i][j][3]);
        }
    }
}

// -------- GEMM TN split-B (SIMT): Cpart[z] = assign[seg z]^T @ feat ----------
__global__ void __launch_bounds__(TPB) k_gemm_tn_seg(
    const float* __restrict__ Asg, const float* __restrict__ Fm,
    float* __restrict__ Cpart) {
    __shared__ float As[16][132];
    __shared__ float Bs[16][132];
    const int tid = threadIdx.x;
    const int tx = tid & 15, ty = tid >> 4;
    const int m0 = blockIdx.x * 128;
    const int n0 = blockIdx.y * 128;
    const int z  = blockIdx.z;
    float acc[8][8];
    #pragma unroll
    for (int i = 0; i < 8; i++)
        #pragma unroll
        for (int j = 0; j < 8; j++) acc[i][j] = 0.f;
    for (int b0 = z * SEGB; b0 < (z + 1) * SEGB; b0 += 16) {
        #pragma unroll
        for (int p = 0; p < 2; p++) {
            int i = tid + p * TPB;
            int bb = i >> 5, v = i & 31;
            *(float4*)(&As[bb][v*4]) = *(const float4*)(Asg + (size_t)(b0 + bb) * KK + m0 + v * 4);
        }
        #pragma unroll
        for (int p = 0; p < 2; p++) {
            int i = tid + p * TPB;
            int bb = i >> 5, v = i & 31;
            *(float4*)(&Bs[bb][v*4]) = *(const float4*)(Fm + (size_t)(b0 + bb) * DD + n0 + v * 4);
        }
        __syncthreads();
        #pragma unroll
        for (int bb = 0; bb < 16; bb++) {
            float a[8], b[8];
            *(float4*)(a)     = *(const float4*)(&As[bb][ty * 8]);
            *(float4*)(a + 4) = *(const float4*)(&As[bb][ty * 8 + 4]);
            *(float4*)(b)     = *(const float4*)(&Bs[bb][tx * 8]);
            *(float4*)(b + 4) = *(const float4*)(&Bs[bb][tx * 8 + 4]);
            #pragma unroll
            for (int i = 0; i < 8; i++)
                #pragma unroll
                for (int j = 0; j < 8; j++) acc[i][j] += a[i] * b[j];
        }
        __syncthreads();
    }
    #pragma unroll
    for (int i = 0; i < 8; i++) {
        float* cp = Cpart + (size_t)z * KK * DD + (size_t)(m0 + ty * 8 + i) * DD + n0 + tx * 8;
        *(float4*)cp       = make_float4(acc[i][0], acc[i][1], acc[i][2], acc[i][3]);
        *(float4*)(cp + 4) = make_float4(acc[i][4], acc[i][5], acc[i][6], acc[i][7]);
    }
}

// ======== tensor-core tf32 negatives GEMM + fused streaming exp-sum ========
__global__ void __launch_bounds__(TPB) k_expsum_tc(
    const float* __restrict__ Am, const float* __restrict__ Qm,
    float* __restrict__ part, int tpc, int nch) {
    extern __shared__ uint32_t dsm[];
    uint32_t* AsU = dsm;               // [128][260]
    uint32_t* BsU = dsm + AS_W;        // [2][128][36]
    float*    red = (float*)(dsm + AS_W + BS_W);  // [128][4]

    const int tid  = threadIdx.x;
    const int lane = tid & 31;
    const int wid  = tid >> 5;
    const int g    = lane >> 2, tg = lane & 3;
    const int wm   = wid >> 2,  wn = wid & 3;
    const int m0w  = wm * 64,   n0w = wn * 32;
    const int m0   = blockIdx.x * 128;
    const int chunk = blockIdx.y;

    #pragma unroll 8
    for (int it = 0; it < 32; it++) {
        int idx = it * TPB + tid;
        int r = idx >> 6, c4 = idx & 63;
        float4 q = *(const float4*)(Am + (size_t)(m0 + r) * DD + c4 * 4);
        uint32_t* p = AsU + r * 260 + c4 * 4;
        p[0] = f2tf32(q.x); p[1] = f2tf32(q.y); p[2] = f2tf32(q.z); p[3] = f2tf32(q.w);
    }

    int rA0[4], rA1[4], rB[4];
    #pragma unroll
    for (int i = 0; i < 4; i++) { rA0[i] = (m0w + i*16 + g) * 260; rA1[i] = rA0[i] + 8*260; }
    #pragma unroll
    for (int j = 0; j < 4; j++) rB[j] = (n0w + j*8 + g) * 36;

    float rp[4][2];
    #pragma unroll
    for (int i = 0; i < 4; i++) { rp[i][0] = 0.f; rp[i][1] = 0.f; }

    int buf = 0;
    __syncthreads();

    for (int t = 0; t < tpc; t++) {
        const int n0 = (chunk * tpc + t) * 128;

        __syncthreads();
        #pragma unroll
        for (int it = 0; it < 4; it++) {
            int idx = it * TPB + tid;
            int r = idx >> 3, c4 = idx & 7;
            float4 q = *(const float4*)(Qm + (size_t)(n0 + r) * DD + c4 * 4);
            uint32_t* p = BsU + buf * 4608 + r * 36 + c4 * 4;
            p[0] = f2tf32(q.x); p[1] = f2tf32(q.y); p[2] = f2tf32(q.z); p[3] = f2tf32(q.w);
        }
        __syncthreads();

        float acc[4][4][4];
        #pragma unroll
        for (int i = 0; i < 4; i++)
            #pragma unroll
            for (int j = 0; j < 4; j++)
                #pragma unroll
                for (int c = 0; c < 4; c++) acc[i][j][c] = 0.f;

        for (int kc = 0; kc < 8; kc++) {
            float4 pre[4];
            if (kc < 7) {
                int k0n = (kc + 1) * 32;
                #pragma unroll
                for (int it = 0; it < 4; it++) {
                    int idx = it * TPB + tid;
                    int r = idx >> 3, c4 = idx & 7;
                    pre[it] = *(const float4*)(Qm + (size_t)(n0 + r) * DD + k0n + c4 * 4);
                }
            }
            const uint32_t* bsb = BsU + buf * 4608;
            #pragma unroll
            for (int ks = 0; ks < 4; ks++) {
                int k = kc * 32 + ks * 8;
                uint32_t a[4][4];
                #pragma unroll
                for (int i = 0; i < 4; i++) {
                    a[i][0] = AsU[rA0[i] + k + tg];
                    a[i][1] = AsU[rA1[i] + k + tg];
                    a[i][2] = AsU[rA0[i] + k + 4 + tg];
                    a[i][3] = AsU[rA1[i] + k + 4 + tg];
                }
                int kl = ks * 8 + tg;
                #pragma unroll
                for (int j = 0; j < 4; j++) {
                    uint32_t b0 = bsb[rB[j] + kl], b1 = bsb[rB[j] + kl + 4];
                    #pragma unroll
                    for (int i = 0; i < 4; i++)
                        mma_tf32(acc[i][j][0], acc[i][j][1], acc[i][j][2], acc[i][j][3],
                                 a[i][0], a[i][1], a[i][2], a[i][3], b0, b1);
                }
            }
            if (kc < 7) {
                #pragma unroll
                for (int it = 0; it < 4; it++) {
                    int idx = it * TPB + tid;
                    int r = idx >> 3, c4 = idx & 7;
                    uint32_t* p = BsU + (buf ^ 1) * 4608 + r * 36 + c4 * 4;
                    p[0] = f2tf32(pre[it].x); p[1] = f2tf32(pre[it].y);
                    p[2] = f2tf32(pre[it].z); p[3] = f2tf32(pre[it].w);
                }
                __syncthreads();
                buf ^= 1;
            }
        }

        #pragma unroll
        for (int i = 0; i < 4; i++) {
            float s0 = 0.f, s1 = 0.f;
            #pragma unroll
            for (int j = 0; j < 4; j++) {
                s0 += __expf(acc[i][j][0] * INVT - INVT) + __expf(acc[i][j][1] * INVT - INVT);
                s1 += __expf(acc[i][j][2] * INVT - INVT) + __expf(acc[i][j][3] * INVT - INVT);
            }
            rp[i][0] += s0; rp[i][1] += s1;
        }
    }

    #pragma unroll
    for (int i = 0; i < 4; i++)
        #pragma unroll
        for (int h = 0; h < 2; h++) {
            float v = rp[i][h];
            v += __shfl_xor_sync(0xffffffffu, v, 1);
            v += __shfl_xor_sync(0xffffffffu, v, 2);
            if (tg == 0) red[(m0w + i*16 + h*8 + g) * 4 + wn] = v;
        }
    __syncthreads();
    if (tid < 128) {
        float s = red[tid*4+0] + red[tid*4+1] + red[tid*4+2] + red[tid*4+3];
        part[(size_t)(m0 + tid) * nch + chunk] = s;
    }
}

// ---------------- gumbel softmax (soft) over K=1024 ----------------
__global__ void k_softmax(const float* __restrict__ logits, const float* __restrict__ u,
                          float* __restrict__ assign) {
    int r = blockIdx.x, t = threadIdx.x;
    float z[4];
    #pragma unroll
    for (int j = 0; j < 4; j++) {
        int k = j * 256 + t;
        size_t i = (size_t)r * KK + k;
        z[j] = (logits[i] + gumbelf_soft(u[i])) * 2.0f;   // 1/GUMBEL_TEMP
    }
    float m = fmaxf(fmaxf(z[0], z[1]), fmaxf(z[2], z[3]));
    m = blockmax256(m);
    float s = 0.f;
    #pragma unroll
    for (int j = 0; j < 4; j++) { z[j] = __expf(z[j] - m); s += z[j]; }
    s = blocksum256(s);
    float inv = 1.0f / s;
    #pragma unroll
    for (int j = 0; j < 4; j++) {
        int k = j * 256 + t;
        assign[(size_t)r * KK + k] = z[j] * inv;
    }
}

// ---------------- hard-path argmax(logits + gumbel), first-index ties ----
__global__ void k_argmax(const float* __restrict__ logits, const float* __restrict__ u,
                         float* __restrict__ out) {
    __shared__ float sb[8]; __shared__ int si[8];
    int r = blockIdx.x, t = threadIdx.x;
    float best = -1e30f; int bi = 0;
    #pragma unroll
    for (int j = 0; j < 4; j++) {
        int k = j * 256 + t;
        size_t i = (size_t)r * KK + k;
        float z = logits[i] + gumbelf(u[i]);
        if (z > best) { best = z; bi = k; }
    }
    #pragma unroll
    for (int o = 16; o; o >>= 1) {
        float ob = __shfl_xor_sync(0xffffffffu, best, o);
        int   oi = __shfl_xor_sync(0xffffffffu, bi, o);
        if (ob > best || (ob == best && oi < bi)) { best = ob; bi = oi; }
    }
    if ((t & 31) == 0) { sb[t >> 5] = best; si[t >> 5] = bi; }
    __syncthreads();
    if (t == 0) {
        #pragma unroll
        for (int w = 1; w < 8; w++)
            if (sb[w] > best || (sb[w] == best && si[w] < bi)) { best = sb[w]; bi = si[w]; }
        out[r] = (float)bi;
    }
}

// ---------------- column sums of assign (normalizer) ----------------
__global__ void k_colsum_part(const float* __restrict__ assign, float* __restrict__ csp) {
    int k = blockIdx.x * TPB + threadIdx.x;
    int c = blockIdx.y;
    float s = 0.f;
    #pragma unroll 4
    for (int b = c * (NB / CSCH); b < (c + 1) * (NB / CSCH); b++)
        s += assign[(size_t)b * KK + k];
    csp[(size_t)c * KK + k] = s;
}
__global__ void k_colsum_fin(const float* __restrict__ csp, float* __restrict__ norm) {
    int k = blockIdx.x * TPB + threadIdx.x;
    float s = 0.f;
    #pragma unroll
    for (int c = 0; c < CSCH; c++) s += csp[(size_t)c * KK + k];
    norm[k] = s;
}

// ---------------- agg_k finish: sum partials, /norm, L2 normalize ----------
__global__ void k_aggk_finish(const float* __restrict__ part, const float* __restrict__ norm,
                              float* __restrict__ dst) {
    int r = blockIdx.x, t = threadIdx.x;
    float v = 0.f;
    #pragma unroll
    for (int s = 0; s < NSEG; s++) v += part[(size_t)s * KK * DD + (size_t)r * DD + t];
    v = v / (norm[r] + 1e-8f);
    float ss = blocksum256(v * v);
    dst[(size_t)r * DD + t] = v * rsqrtf(fmaxf(ss, 1e-12f));
}

// ------------- per-row CE: lp = lpos/T - logsumexp (shifted) -------------
__global__ void k_ce_row(const float* __restrict__ q, const float* __restrict__ kv,
                         const float* __restrict__ part, int nch,
                         float* __restrict__ lp) {
    int r = blockIdx.x, t = threadIdx.x;
    float v = q[(size_t)r * DD + t] * kv[(size_t)r * DD + t];
    float lpos = blocksum256(v);
    if (t == 0) {
        float S = expf(lpos * INVT - INVT);
        for (int c = 0; c < nch; c++) S += part[(size_t)r * nch + c];
        lp[r] = lpos * INVT - INVT - logf(S);
    }
}

// ---------------- final scalar loss ----------------
__global__ void k_loss(const float* __restrict__ lpn, const float* __restrict__ lpk,
                       float* __restrict__ out) {
    int t = threadIdx.x;
    float s1 = 0.f;
    for (int i = t; i < NB; i += TPB) s1 += lpn[i];
    s1 = blocksum256(s1);
    float s2 = 0.f;
    for (int i = t; i < KK; i += TPB) s2 += lpk[i];
    s2 = blocksum256(s2);
    if (t == 0) out[0] = -(s1 / NB) - (s2 / KK);
}

// ============================ launcher ============================
extern "C" void kernel_launch(void* const* d_in, const int* in_sizes, int n_in,
                              void* d_out, int out_size) {
    const float* x1    = (const float*)d_in[0];
    const float* x2    = (const float*)d_in[1];
    const float* W1    = (const float*)d_in[2];
    const float* W2    = (const float*)d_in[3];
    const float* ctx1r = (const float*)d_in[4];
    const float* ctx2r = (const float*)d_in[5];
    const float* qn_r  = (const float*)d_in[6];
    const float* qk_r  = (const float*)d_in[7];
    const float* u1a   = (const float*)d_in[8];
    const float* u1b   = (const float*)d_in[9];
    const float* u2a   = (const float*)d_in[10];
    const float* u2b   = (const float*)d_in[11];
    const float* qnz   = (const float*)d_in[12];
    (void)u2b; (void)in_sizes; (void)n_in; (void)out_size;

    cudaFuncSetAttribute(k_expsum_tc, cudaFuncAttributeMaxDynamicSharedMemorySize, SMEM_TC);
    cudaFuncSetAttribute(k_gemm_nt3, cudaFuncAttributeMaxDynamicSharedMemorySize, SMEM_NT3);

    float* S;
    cudaGetSymbolAddress((void**)&S, g_scratch);
    float* tmp    = S + O_TMP;
    float* feat1  = S + O_FEAT1;
    float* ctx1   = S + O_CTX1;
    float* ctx2   = S + O_CTX2;
    float* qn     = S + O_QN;
    float* qkq    = S + O_QKQ;
    float* logits = S + O_LOGITS;
    float* assign = S + O_ASSIGN;
    float* aggk1  = S + O_AGGK1;
    float* aggp   = S + O_AGGP;
    float* csp    = S + O_CSP;
    float* normk  = S + O_NORMK;
    float* lpn    = S + O_LPN;
    float* lpk    = S + O_LPK;
    float* partn  = S + O_PARTN;
    float* partk  = S + O_PARTK;
    float* w1t    = S + O_W1T;
    float* w2t    = S + O_W2T;

    float* outF     = (float*)d_out;
    float* outAsg   = outF;                         // assignment [4096]
    float* feat2    = outF + NB;                    // agg_n_2 = feat2 [4096,256]
    float* aggk2    = outF + NB + (size_t)NB * DD;  // agg_k_2 [1024,256]
    float* outLoss  = outF + NB + (size_t)NB * DD + (size_t)KK * DD;

    // W transposes (once per call; cheap)
    k_transpose<<<dim3(DD/32, DIN/32), dim3(32, 8)>>>(W1, w1t, DIN, DD);
    k_transpose<<<dim3(DD/32, DIN/32), dim3(32, 8)>>>(W2, w2t, DIN, DD);

    // encoders (3xTF32 NT vs Wt) + norms
    k_gemm_nt3<<<dim3(32, 2), TPB, SMEM_NT3>>>(x1, w1t, tmp, DIN, DD);
    k_rownorm_w<<<NB/8, TPB>>>(tmp, feat1);
    k_gemm_nt3<<<dim3(32, 2), TPB, SMEM_NT3>>>(x2, w2t, tmp, DIN, DD);
    k_rownorm_w<<<NB/8, TPB>>>(tmp, feat2);
    k_rownorm_w<<<KK/8, TPB>>>(ctx1r, ctx1);
    k_rownorm_w<<<KK/8, TPB>>>(ctx2r, ctx2);
    k_rownorm_w<<<LL/8, TPB>>>(qn_r, qn);
    k_rownorm_queue_w<<<QKR/8, TPB>>>(qk_r, qnz, qkq);

    // view 1: logits (3xTF32), soft assign, hard argmax (output), agg_k_1
    k_gemm_nt3<<<dim3(32, 8), TPB, SMEM_NT3>>>(feat1, ctx1, logits, DD, KK);
    k_softmax<<<NB, TPB>>>(logits, u1a, assign);
    k_argmax<<<NB, TPB>>>(logits, u1b, outAsg);
    k_colsum_part<<<dim3(KK / TPB, CSCH), TPB>>>(assign, csp);
    k_colsum_fin<<<KK / TPB, TPB>>>(csp, normk);
    k_gemm_tn_seg<<<dim3(8, 2, NSEG), TPB>>>(assign, feat1, aggp);
    k_aggk_finish<<<KK, TPB>>>(aggp, normk, aggk1);

    // view 2
    k_gemm_nt3<<<dim3(32, 8), TPB, SMEM_NT3>>>(feat2, ctx2, logits, DD, KK);
    k_softmax<<<NB, TPB>>>(logits, u2a, assign);
    k_colsum_part<<<dim3(KK / TPB, CSCH), TPB>>>(assign, csp);
    k_colsum_fin<<<KK / TPB, TPB>>>(csp, normk);
    k_gemm_tn_seg<<<dim3(8, 2, NSEG), TPB>>>(assign, feat2, aggp);
    k_aggk_finish<<<KK, TPB>>>(aggp, normk, aggk2);

    // loss_n : negatives vs queue_n (tensor-core tf32, fused exp-sum)
    k_expsum_tc<<<dim3(NB / 128, NCHN), TPB, SMEM_TC>>>(feat1, qn, partn, TPCN, NCHN);
    k_ce_row<<<NB, TPB>>>(feat1, feat2, partn, NCHN, lpn);

    // loss_k : negatives vs perturbed queue_k (tensor-core tf32)
    k_expsum_tc<<<dim3(KK / 128, NCHK), TPB, SMEM_TC>>>(aggk1, qkq, partk, TPCK, NCHK);
    k_ce_row<<<KK, TPB>>>(aggk1, aggk2, partk, NCHK, lpk);

    k_loss<<<1, TPB>>>(lpn, lpk, outLoss);
}

// round 9
// speedup vs baseline: 2.4291x; 1.0736x over previous
#include <cuda_runtime.h>
#include <cuda_fp16.h>
#include <math.h>
#include <stdint.h>

#define TPB 256

// ---- problem sizes ----
constexpr int NB  = 4096;   // batch
constexpr int DIN = 1024;
constexpr int DD  = 256;
constexpr int KK  = 1024;   // clusters
constexpr int LL  = 32768;  // queue_n rows
constexpr int QKR = 4096;   // queue_k rows

constexpr int NSEG = 8;             // split-B segments for agg GEMM
constexpr int SEGB = NB / NSEG;     // 512
constexpr int NCHN = 16, TPCN = 16; // loss_n chunks/tiles
constexpr int NCHK = 8,  TPCK = 4;  // loss_k chunks/tiles
constexpr int CSCH = 32;            // colsum b-chunks

constexpr float INVT = 1.0f / 0.07f;

// fp16 expsum smem (uint32 words): A [128][132], B [2][128][20], red [128][4]
constexpr int ASH_W  = 128 * 132;
constexpr int BSH_W  = 2 * 128 * 20;
constexpr int REDH_W = 128 * 4;
constexpr int SMEM_H = (ASH_W + BSH_W + REDH_W) * 4;   // 90112 B -> 2 CTAs/SM

// nt3 smem: 2 bufs x (AH, AL, BH, BL) each 128x36 words
constexpr int G_CH = 128 * 36;
constexpr int SMEM_NT3 = 2 * 4 * G_CH * 4;             // 147456 B

// ---- scratch offsets (floats) ----
constexpr size_t O_TMP    = 0;
constexpr size_t O_FEAT1  = O_TMP    + (size_t)NB*DD;
constexpr size_t O_CTX1   = O_FEAT1  + (size_t)NB*DD;
constexpr size_t O_CTX2   = O_CTX1   + (size_t)KK*DD;
constexpr size_t O_QN     = O_CTX2   + (size_t)KK*DD;
constexpr size_t O_QKQ    = O_QN     + (size_t)LL*DD;
constexpr size_t O_LOGITS = O_QKQ    + (size_t)QKR*DD;
constexpr size_t O_ASSIGN = O_LOGITS + (size_t)NB*KK;
constexpr size_t O_AGGK1  = O_ASSIGN + (size_t)NB*KK;
constexpr size_t O_AGGP   = O_AGGK1  + (size_t)KK*DD;
constexpr size_t O_CSP    = O_AGGP   + (size_t)NSEG*KK*DD;
constexpr size_t O_NORMK  = O_CSP    + (size_t)CSCH*KK;
constexpr size_t O_LPN    = O_NORMK  + KK;
constexpr size_t O_LPK    = O_LPN    + NB;
constexpr size_t O_PARTN  = O_LPK    + KK;
constexpr size_t O_PARTK  = O_PARTN  + (size_t)NB*NCHN;
constexpr size_t O_W1T    = O_PARTK  + (size_t)KK*NCHK;
constexpr size_t O_W2T    = O_W1T    + (size_t)DD*DIN;
constexpr size_t O_END    = O_W2T    + (size_t)DD*DIN;

__device__ float g_scratch[O_END];

// ---------------- helpers ----------------
__device__ __forceinline__ float gumbelf(float u) {         // accurate (argmax path)
    u = u * (1.0f - 2e-6f) + 1e-6f;
    return -logf(-logf(u));
}
__device__ __forceinline__ float gumbelf_soft(float u) {    // soft path: fast outer log
    u = u * (1.0f - 2e-6f) + 1e-6f;
    return -__logf(-logf(u));
}

__device__ __forceinline__ uint32_t f2tf32(float x) {
    uint32_t u;
    asm("cvt.rna.tf32.f32 %0, %1;" : "=r"(u) : "f"(x));
    return u;
}

__device__ __forceinline__ uint32_t pack_h2(float a, float b) {
    __half2 h = __floats2half2_rn(a, b);   // low = a, high = b
    return *(uint32_t*)&h;
}

__device__ __forceinline__ void mma_tf32(
    float& c0, float& c1, float& c2, float& c3,
    uint32_t a0, uint32_t a1, uint32_t a2, uint32_t a3,
    uint32_t b0, uint32_t b1) {
    asm volatile(
        "mma.sync.aligned.m16n8k8.row.col.f32.tf32.tf32.f32 "
        "{%0,%1,%2,%3}, {%4,%5,%6,%7}, {%8,%9}, {%0,%1,%2,%3};\n"
        : "+f"(c0), "+f"(c1), "+f"(c2), "+f"(c3)
        : "r"(a0), "r"(a1), "r"(a2), "r"(a3), "r"(b0), "r"(b1));
}

__device__ __forceinline__ void mma_f16(
    float& c0, float& c1, float& c2, float& c3,
    uint32_t a0, uint32_t a1, uint32_t a2, uint32_t a3,
    uint32_t b0, uint32_t b1) {
    asm volatile(
        "mma.sync.aligned.m16n8k16.row.col.f32.f16.f16.f32 "
        "{%0,%1,%2,%3}, {%4,%5,%6,%7}, {%8,%9}, {%0,%1,%2,%3};\n"
        : "+f"(c0), "+f"(c1), "+f"(c2), "+f"(c3)
        : "r"(a0), "r"(a1), "r"(a2), "r"(a3), "r"(b0), "r"(b1));
}

__device__ __forceinline__ float blocksum256(float v) {
    __shared__ float sh_s[8];
    #pragma unroll
    for (int o = 16; o; o >>= 1) v += __shfl_xor_sync(0xffffffffu, v, o);
    if ((threadIdx.x & 31) == 0) sh_s[threadIdx.x >> 5] = v;
    __syncthreads();
    float s = 0.f;
    #pragma unroll
    for (int i = 0; i < 8; i++) s += sh_s[i];
    __syncthreads();
    return s;
}

__device__ __forceinline__ float blockmax256(float v) {
    __shared__ float sh_m[8];
    #pragma unroll
    for (int o = 16; o; o >>= 1) v = fmaxf(v, __shfl_xor_sync(0xffffffffu, v, o));
    if ((threadIdx.x & 31) == 0) sh_m[threadIdx.x >> 5] = v;
    __syncthreads();
    float s = sh_m[0];
    #pragma unroll
    for (int i = 1; i < 8; i++) s = fmaxf(s, sh_m[i]);
    __syncthreads();
    return s;
}

// ---------- warp-per-row L2 normalize (8 rows/block, float4) ----------
__global__ void k_rownorm_w(const float* __restrict__ src, float* __restrict__ dst) {
    int wid = threadIdx.x >> 5, lane = threadIdx.x & 31;
    int row = blockIdx.x * 8 + wid;
    const float4* s = (const float4*)(src + (size_t)row * DD);
    float4 a = s[lane], b = s[lane + 32];
    float ss = a.x*a.x + a.y*a.y + a.z*a.z + a.w*a.w
             + b.x*b.x + b.y*b.y + b.z*b.z + b.w*b.w;
    #pragma unroll
    for (int o = 16; o; o >>= 1) ss += __shfl_xor_sync(0xffffffffu, ss, o);
    float r = rsqrtf(fmaxf(ss, 1e-12f));
    float4* d = (float4*)(dst + (size_t)row * DD);
    d[lane]      = make_float4(a.x*r, a.y*r, a.z*r, a.w*r);
    d[lane + 32] = make_float4(b.x*r, b.y*r, b.z*r, b.w*r);
}

// queue = l2norm(2*queue_k + qnoise), warp-per-row
__global__ void k_rownorm_queue_w(const float* __restrict__ qk, const float* __restrict__ nz,
                                  float* __restrict__ dst) {
    int wid = threadIdx.x >> 5, lane = threadIdx.x & 31;
    int row = blockIdx.x * 8 + wid;
    const float4* q = (const float4*)(qk + (size_t)row * DD);
    const float4* n = (const float4*)(nz + (size_t)row * DD);
    float4 qa = q[lane], qb = q[lane + 32];
    float4 na = n[lane], nb = n[lane + 32];
    float4 a = make_float4(qa.x+na.x+qa.x, qa.y+na.y+qa.y, qa.z+na.z+qa.z, qa.w+na.w+qa.w);
    float4 b = make_float4(qb.x+nb.x+qb.x, qb.y+nb.y+qb.y, qb.z+nb.z+qb.z, qb.w+nb.w+qb.w);
    float ss = a.x*a.x + a.y*a.y + a.z*a.z + a.w*a.w
             + b.x*b.x + b.y*b.y + b.z*b.z + b.w*b.w;
    #pragma unroll
    for (int o = 16; o; o >>= 1) ss += __shfl_xor_sync(0xffffffffu, ss, o);
    float r = rsqrtf(fmaxf(ss, 1e-12f));
    float4* d = (float4*)(dst + (size_t)row * DD);
    d[lane]      = make_float4(a.x*r, a.y*r, a.z*r, a.w*r);
    d[lane + 32] = make_float4(b.x*r, b.y*r, b.z*r, b.w*r);
}

// ---------------- 32x32 tiled transpose: dst[C,R] = src[R,C]^T -------------
__global__ void k_transpose(const float* __restrict__ src, float* __restrict__ dst,
                            int R, int C) {
    __shared__ float t[32][33];
    int bx = blockIdx.x * 32, by = blockIdx.y * 32;
    int tx = threadIdx.x, ty = threadIdx.y;
    #pragma unroll
    for (int i = 0; i < 4; i++)
        t[ty + i*8][tx] = src[(size_t)(by + ty + i*8) * C + bx + tx];
    __syncthreads();
    #pragma unroll
    for (int i = 0; i < 4; i++)
        dst[(size_t)(bx + ty + i*8) * R + by + tx] = t[tx][ty + i*8];
}

// ======= 3xTF32 tensor-core GEMM NT: C[M,N] = A[M,K] @ B[N,K]^T =======
__global__ void __launch_bounds__(TPB) k_gemm_nt3(
    const float* __restrict__ A, const float* __restrict__ B,
    float* __restrict__ C, int K, int N) {
    extern __shared__ uint32_t sm3[];
    const int tid  = threadIdx.x;
    const int lane = tid & 31;
    const int wid  = tid >> 5;
    const int g    = lane >> 2, tg = lane & 3;
    const int wm   = wid >> 2,  wn = wid & 3;
    const int m0w  = wm * 64,   n0w = wn * 32;
    const int m0   = blockIdx.x * 128, n0 = blockIdx.y * 128;
    const int KC   = K >> 5;

    float acc[4][4][4];
    #pragma unroll
    for (int i = 0; i < 4; i++)
        #pragma unroll
        for (int j = 0; j < 4; j++)
            #pragma unroll
            for (int c = 0; c < 4; c++) acc[i][j][c] = 0.f;

    #pragma unroll
    for (int it = 0; it < 4; it++) {
        int idx = it * TPB + tid;
        int r = idx >> 3, c4 = idx & 7;
        float4 qa = *(const float4*)(A + (size_t)(m0 + r) * K + c4 * 4);
        float4 qb = *(const float4*)(B + (size_t)(n0 + r) * K + c4 * 4);
        uint32_t* pah = sm3 + r * 36 + c4 * 4;
        uint32_t* pal = pah + G_CH;
        uint32_t* pbh = pah + 2 * G_CH;
        uint32_t* pbl = pah + 3 * G_CH;
        float va[4] = {qa.x, qa.y, qa.z, qa.w};
        float vb[4] = {qb.x, qb.y, qb.z, qb.w};
        #pragma unroll
        for (int c = 0; c < 4; c++) {
            uint32_t h = f2tf32(va[c]);
            pah[c] = h; pal[c] = f2tf32(va[c] - __uint_as_float(h));
            uint32_t hb = f2tf32(vb[c]);
            pbh[c] = hb; pbl[c] = f2tf32(vb[c] - __uint_as_float(hb));
        }
    }
    __syncthreads();

    int buf = 0;
    for (int kc = 0; kc < KC; kc++) {
        float4 pa[4], pb[4];
        if (kc < KC - 1) {
            int k0n = (kc + 1) * 32;
            #pragma unroll
            for (int it = 0; it < 4; it++) {
                int idx = it * TPB + tid;
                int r = idx >> 3, c4 = idx & 7;
                pa[it] = *(const float4*)(A + (size_t)(m0 + r) * K + k0n + c4 * 4);
                pb[it] = *(const float4*)(B + (size_t)(n0 + r) * K + k0n + c4 * 4);
            }
        }
        const uint32_t* AH = sm3 + buf * 4 * G_CH;
        const uint32_t* AL = AH + G_CH;
        const uint32_t* BH = AH + 2 * G_CH;
        const uint32_t* BL = AH + 3 * G_CH;
        #pragma unroll
        for (int ks = 0; ks < 4; ks++) {
            int kk = ks * 8 + tg;
            uint32_t ah[4][4], al[4][4];
            #pragma unroll
            for (int i = 0; i < 4; i++) {
                int base = (m0w + i * 16 + g) * 36;
                ah[i][0] = AH[base + kk];          ah[i][1] = AH[base + 8*36 + kk];
                ah[i][2] = AH[base + kk + 4];      ah[i][3] = AH[base + 8*36 + kk + 4];
                al[i][0] = AL[base + kk];          al[i][1] = AL[base + 8*36 + kk];
                al[i][2] = AL[base + kk + 4];      al[i][3] = AL[base + 8*36 + kk + 4];
            }
            #pragma unroll
            for (int j = 0; j < 4; j++) {
                int bbase = (n0w + j * 8 + g) * 36;
                uint32_t bh0 = BH[bbase + kk], bh1 = BH[bbase + kk + 4];
                uint32_t bl0 = BL[bbase + kk], bl1 = BL[bbase + kk + 4];
                #pragma unroll
                for (int i = 0; i < 4; i++) {
                    mma_tf32(acc[i][j][0], acc[i][j][1], acc[i][j][2], acc[i][j][3],
                             ah[i][0], ah[i][1], ah[i][2], ah[i][3], bh0, bh1);
                    mma_tf32(acc[i][j][0], acc[i][j][1], acc[i][j][2], acc[i][j][3],
                             ah[i][0], ah[i][1], ah[i][2], ah[i][3], bl0, bl1);
                    mma_tf32(acc[i][j][0], acc[i][j][1], acc[i][j][2], acc[i][j][3],
                             al[i][0], al[i][1], al[i][2], al[i][3], bh0, bh1);
                }
            }
        }
        if (kc < KC - 1) {
            uint32_t* dst = sm3 + (buf ^ 1) * 4 * G_CH;
            #pragma unroll
            for (int it = 0; it < 4; it++) {
                int idx = it * TPB + tid;
                int r = idx >> 3, c4 = idx & 7;
                uint32_t* pah = dst + r * 36 + c4 * 4;
                uint32_t* pal = pah + G_CH;
                uint32_t* pbh = pah + 2 * G_CH;
                uint32_t* pbl = pah + 3 * G_CH;
                float va[4] = {pa[it].x, pa[it].y, pa[it].z, pa[it].w};
                float vb[4] = {pb[it].x, pb[it].y, pb[it].z, pb[it].w};
                #pragma unroll
                for (int c = 0; c < 4; c++) {
                    uint32_t h = f2tf32(va[c]);
                    pah[c] = h; pal[c] = f2tf32(va[c] - __uint_as_float(h));
                    uint32_t hb = f2tf32(vb[c]);
                    pbh[c] = hb; pbl[c] = f2tf32(vb[c] - __uint_as_float(hb));
                }
            }
            __syncthreads();
            buf ^= 1;
        }
    }

    #pragma unroll
    for (int i = 0; i < 4; i++) {
        int row = m0 + m0w + i * 16 + g;
        #pragma unroll
        for (int j = 0; j < 4; j++) {
            int col = n0 + n0w + j * 8 + tg * 2;
            *(float2*)(C + (size_t)row * N + col)       = make_float2(acc[i][j][0], acc[i][j][1]);
            *(float2*)(C + (size_t)(row + 8) * N + col) = make_float2(acc[i][j][2], acc[i][j][3]);
        }
    }
}

// -------- GEMM TN split-B (SIMT): Cpart[z] = assign[seg z]^T @ feat ----------
__global__ void __launch_bounds__(TPB) k_gemm_tn_seg(
    const float* __restrict__ Asg, const float* __restrict__ Fm,
    float* __restrict__ Cpart) {
    __shared__ float As[16][132];
    __shared__ float Bs[16][132];
    const int tid = threadIdx.x;
    const int tx = tid & 15, ty = tid >> 4;
    const int m0 = blockIdx.x * 128;
    const int n0 = blockIdx.y * 128;
    const int z  = blockIdx.z;
    float acc[8][8];
    #pragma unroll
    for (int i = 0; i < 8; i++)
        #pragma unroll
        for (int j = 0; j < 8; j++) acc[i][j] = 0.f;
    for (int b0 = z * SEGB; b0 < (z + 1) * SEGB; b0 += 16) {
        #pragma unroll
        for (int p = 0; p < 2; p++) {
            int i = tid + p * TPB;
            int bb = i >> 5, v = i & 31;
            *(float4*)(&As[bb][v*4]) = *(const float4*)(Asg + (size_t)(b0 + bb) * KK + m0 + v * 4);
        }
        #pragma unroll
        for (int p = 0; p < 2; p++) {
            int i = tid + p * TPB;
            int bb = i >> 5, v = i & 31;
            *(float4*)(&Bs[bb][v*4]) = *(const float4*)(Fm + (size_t)(b0 + bb) * DD + n0 + v * 4);
        }
        __syncthreads();
        #pragma unroll
        for (int bb = 0; bb < 16; bb++) {
            float a[8], b[8];
            *(float4*)(a)     = *(const float4*)(&As[bb][ty * 8]);
            *(float4*)(a + 4) = *(const float4*)(&As[bb][ty * 8 + 4]);
            *(float4*)(b)     = *(const float4*)(&Bs[bb][tx * 8]);
            *(float4*)(b + 4) = *(const float4*)(&Bs[bb][tx * 8 + 4]);
            #pragma unroll
            for (int i = 0; i < 8; i++)
                #pragma unroll
                for (int j = 0; j < 8; j++) acc[i][j] += a[i] * b[j];
        }
        __syncthreads();
    }
    #pragma unroll
    for (int i = 0; i < 8; i++) {
        float* cp = Cpart + (size_t)z * KK * DD + (size_t)(m0 + ty * 8 + i) * DD + n0 + tx * 8;
        *(float4*)cp       = make_float4(acc[i][0], acc[i][1], acc[i][2], acc[i][3]);
        *(float4*)(cp + 4) = make_float4(acc[i][4], acc[i][5], acc[i][6], acc[i][7]);
    }
}

// ===== fp16 tensor-core negatives GEMM + fused streaming exp-sum =====
// A [128 rows] resident as half in smem; B 32-k chunks double-buffered.
// m16n8k16 fragments; ~88KB smem -> 2 CTAs/SM.
__global__ void __launch_bounds__(TPB) k_expsum_h(
    const float* __restrict__ Am, const float* __restrict__ Qm,
    float* __restrict__ part, int tpc, int nch) {
    extern __shared__ uint32_t dsm[];
    uint32_t* AsU = dsm;                 // [128][132] words (half2-packed)
    uint32_t* BsU = dsm + ASH_W;         // [2][128][20]
    float*    red = (float*)(dsm + ASH_W + BSH_W);  // [128][4]

    const int tid  = threadIdx.x;
    const int lane = tid & 31;
    const int wid  = tid >> 5;
    const int g    = lane >> 2, tg = lane & 3;
    const int wm   = wid >> 2,  wn = wid & 3;
    const int m0w  = wm * 64,   n0w = wn * 32;
    const int m0   = blockIdx.x * 128;
    const int chunk = blockIdx.y;

    // Load A [128 x 256] fp32 -> half2 smem (32 iters x float4 = 2 words)
    #pragma unroll 8
    for (int it = 0; it < 32; it++) {
        int idx = it * TPB + tid;
        int r = idx >> 6, c4 = idx & 63;
        float4 q = *(const float4*)(Am + (size_t)(m0 + r) * DD + c4 * 4);
        uint32_t* p = AsU + r * 132 + c4 * 2;
        p[0] = pack_h2(q.x, q.y); p[1] = pack_h2(q.z, q.w);
    }

    int rA0[4], rA1[4], rB[4];
    #pragma unroll
    for (int i = 0; i < 4; i++) { rA0[i] = (m0w + i*16 + g) * 132; rA1[i] = rA0[i] + 8*132; }
    #pragma unroll
    for (int j = 0; j < 4; j++) rB[j] = (n0w + j*8 + g) * 20;

    float rp[4][2];
    #pragma unroll
    for (int i = 0; i < 4; i++) { rp[i][0] = 0.f; rp[i][1] = 0.f; }

    int buf = 0;
    __syncthreads();   // A visible

    for (int t = 0; t < tpc; t++) {
        const int n0 = (chunk * tpc + t) * 128;

        __syncthreads();  // prior tile's reads of Bs[buf] complete
        #pragma unroll
        for (int it = 0; it < 4; it++) {
            int idx = it * TPB + tid;
            int r = idx >> 3, c4 = idx & 7;
            float4 q = *(const float4*)(Qm + (size_t)(n0 + r) * DD + c4 * 4);
            uint32_t* p = BsU + buf * 2560 + r * 20 + c4 * 2;
            p[0] = pack_h2(q.x, q.y); p[1] = pack_h2(q.z, q.w);
        }
        __syncthreads();

        float acc[4][4][4];
        #pragma unroll
        for (int i = 0; i < 4; i++)
            #pragma unroll
            for (int j = 0; j < 4; j++)
                #pragma unroll
                for (int c = 0; c < 4; c++) acc[i][j][c] = 0.f;

        for (int kc = 0; kc < 8; kc++) {       // 8 chunks x 32 k
            float4 pre[4];
            if (kc < 7) {
                int k0n = (kc + 1) * 32;
                #pragma unroll
                for (int it = 0; it < 4; it++) {
                    int idx = it * TPB + tid;
                    int r = idx >> 3, c4 = idx & 7;
                    pre[it] = *(const float4*)(Qm + (size_t)(n0 + r) * DD + k0n + c4 * 4);
                }
            }
            const uint32_t* bsb = BsU + buf * 2560;
            #pragma unroll
            for (int kt = 0; kt < 2; kt++) {   // 2 x k16
                int kw = kc * 16 + kt * 8;     // word offset within row
                uint32_t a[4][4];
                #pragma unroll
                for (int i = 0; i < 4; i++) {
                    a[i][0] = AsU[rA0[i] + kw + tg];
                    a[i][1] = AsU[rA1[i] + kw + tg];
                    a[i][2] = AsU[rA0[i] + kw + 4 + tg];
                    a[i][3] = AsU[rA1[i] + kw + 4 + tg];
                }
                int kl = kt * 8 + tg;
                #pragma unroll
                for (int j = 0; j < 4; j++) {
                    uint32_t b0 = bsb[rB[j] + kl], b1 = bsb[rB[j] + kl + 4];
                    #pragma unroll
                    for (int i = 0; i < 4; i++)
                        mma_f16(acc[i][j][0], acc[i][j][1], acc[i][j][2], acc[i][j][3],
                                a[i][0], a[i][1], a[i][2], a[i][3], b0, b1);
                }
            }
            if (kc < 7) {
                #pragma unroll
                for (int it = 0; it < 4; it++) {
                    int idx = it * TPB + tid;
                    int r = idx >> 3, c4 = idx & 7;
                    uint32_t* p = BsU + (buf ^ 1) * 2560 + r * 20 + c4 * 2;
                    p[0] = pack_h2(pre[it].x, pre[it].y);
                    p[1] = pack_h2(pre[it].z, pre[it].w);
                }
                __syncthreads();
                buf ^= 1;
            }
        }

        // fused exp-sum: c0/c1 -> row g, c2/c3 -> row g+8 (cols all summed)
        #pragma unroll
        for (int i = 0; i < 4; i++) {
            float s0 = 0.f, s1 = 0.f;
            #pragma unroll
            for (int j = 0; j < 4; j++) {
                s0 += __expf(acc[i][j][0] * INVT - INVT) + __expf(acc[i][j][1] * INVT - INVT);
                s1 += __expf(acc[i][j][2] * INVT - INVT) + __expf(acc[i][j][3] * INVT - INVT);
            }
            rp[i][0] += s0; rp[i][1] += s1;
        }
    }

    // reduce 4 lanes per row, then across 4 n-warps
    #pragma unroll
    for (int i = 0; i < 4; i++)
        #pragma unroll
        for (int h = 0; h < 2; h++) {
            float v = rp[i][h];
            v += __shfl_xor_sync(0xffffffffu, v, 1);
            v += __shfl_xor_sync(0xffffffffu, v, 2);
            if (tg == 0) red[(m0w + i*16 + h*8 + g) * 4 + wn] = v;
        }
    __syncthreads();
    if (tid < 128) {
        float s = red[tid*4+0] + red[tid*4+1] + red[tid*4+2] + red[tid*4+3];
        part[(size_t)(m0 + tid) * nch + chunk] = s;
    }
}

// ---------------- gumbel softmax (soft) over K=1024 ----------------
__global__ void k_softmax(const float* __restrict__ logits, const float* __restrict__ u,
                          float* __restrict__ assign) {
    int r = blockIdx.x, t = threadIdx.x;
    float z[4];
    #pragma unroll
    for (int j = 0; j < 4; j++) {
        int k = j * 256 + t;
        size_t i = (size_t)r * KK + k;
        z[j] = (logits[i] + gumbelf_soft(u[i])) * 2.0f;   // 1/GUMBEL_TEMP
    }
    float m = fmaxf(fmaxf(z[0], z[1]), fmaxf(z[2], z[3]));
    m = blockmax256(m);
    float s = 0.f;
    #pragma unroll
    for (int j = 0; j < 4; j++) { z[j] = __expf(z[j] - m); s += z[j]; }
    s = blocksum256(s);
    float inv = 1.0f / s;
    #pragma unroll
    for (int j = 0; j < 4; j++) {
        int k = j * 256 + t;
        assign[(size_t)r * KK + k] = z[j] * inv;
    }
}

// ---------------- hard-path argmax(logits + gumbel), first-index ties ----
__global__ void k_argmax(const float* __restrict__ logits, const float* __restrict__ u,
                         float* __restrict__ out) {
    __shared__ float sb[8]; __shared__ int si[8];
    int r = blockIdx.x, t = threadIdx.x;
    float best = -1e30f; int bi = 0;
    #pragma unroll
    for (int j = 0; j < 4; j++) {
        int k = j * 256 + t;
        size_t i = (size_t)r * KK + k;
        float z = logits[i] + gumbelf(u[i]);
        if (z > best) { best = z; bi = k; }
    }
    #pragma unroll
    for (int o = 16; o; o >>= 1) {
        float ob = __shfl_xor_sync(0xffffffffu, best, o);
        int   oi = __shfl_xor_sync(0xffffffffu, bi, o);
        if (ob > best || (ob == best && oi < bi)) { best = ob; bi = oi; }
    }
    if ((t & 31) == 0) { sb[t >> 5] = best; si[t >> 5] = bi; }
    __syncthreads();
    if (t == 0) {
        #pragma unroll
        for (int w = 1; w < 8; w++)
            if (sb[w] > best || (sb[w] == best && si[w] < bi)) { best = sb[w]; bi = si[w]; }
        out[r] = (float)bi;
    }
}

// ---------------- column sums of assign (normalizer) ----------------
__global__ void k_colsum_part(const float* __restrict__ assign, float* __restrict__ csp) {
    int k = blockIdx.x * TPB + threadIdx.x;
    int c = blockIdx.y;
    float s = 0.f;
    #pragma unroll 4
    for (int b = c * (NB / CSCH); b < (c + 1) * (NB / CSCH); b++)
        s += assign[(size_t)b * KK + k];
    csp[(size_t)c * KK + k] = s;
}
__global__ void k_colsum_fin(const float* __restrict__ csp, float* __restrict__ norm) {
    int k = blockIdx.x * TPB + threadIdx.x;
    float s = 0.f;
    #pragma unroll
    for (int c = 0; c < CSCH; c++) s += csp[(size_t)c * KK + k];
    norm[k] = s;
}

// ---------------- agg_k finish: sum partials, /norm, L2 normalize ----------
__global__ void k_aggk_finish(const float* __restrict__ part, const float* __restrict__ norm,
                              float* __restrict__ dst) {
    int r = blockIdx.x, t = threadIdx.x;
    float v = 0.f;
    #pragma unroll
    for (int s = 0; s < NSEG; s++) v += part[(size_t)s * KK * DD + (size_t)r * DD + t];
    v = v / (norm[r] + 1e-8f);
    float ss = blocksum256(v * v);
    dst[(size_t)r * DD + t] = v * rsqrtf(fmaxf(ss, 1e-12f));
}

// ------------- per-row CE: lp = lpos/T - logsumexp (shifted) -------------
__global__ void k_ce_row(const float* __restrict__ q, const float* __restrict__ kv,
                         const float* __restrict__ part, int nch,
                         float* __restrict__ lp) {
    int r = blockIdx.x, t = threadIdx.x;
    float v = q[(size_t)r * DD + t] * kv[(size_t)r * DD + t];
    float lpos = blocksum256(v);
    if (t == 0) {
        float S = expf(lpos * INVT - INVT);
        for (int c = 0; c < nch; c++) S += part[(size_t)r * nch + c];
        lp[r] = lpos * INVT - INVT - logf(S);
    }
}

// ---------------- final scalar loss ----------------
__global__ void k_loss(const float* __restrict__ lpn, const float* __restrict__ lpk,
                       float* __restrict__ out) {
    int t = threadIdx.x;
    float s1 = 0.f;
    for (int i = t; i < NB; i += TPB) s1 += lpn[i];
    s1 = blocksum256(s1);
    float s2 = 0.f;
    for (int i = t; i < KK; i += TPB) s2 += lpk[i];
    s2 = blocksum256(s2);
    if (t == 0) out[0] = -(s1 / NB) - (s2 / KK);
}

// ============================ launcher ============================
extern "C" void kernel_launch(void* const* d_in, const int* in_sizes, int n_in,
                              void* d_out, int out_size) {
    const float* x1    = (const float*)d_in[0];
    const float* x2    = (const float*)d_in[1];
    const float* W1    = (const float*)d_in[2];
    const float* W2    = (const float*)d_in[3];
    const float* ctx1r = (const float*)d_in[4];
    const float* ctx2r = (const float*)d_in[5];
    const float* qn_r  = (const float*)d_in[6];
    const float* qk_r  = (const float*)d_in[7];
    const float* u1a   = (const float*)d_in[8];
    const float* u1b   = (const float*)d_in[9];
    const float* u2a   = (const float*)d_in[10];
    const float* u2b   = (const float*)d_in[11];
    const float* qnz   = (const float*)d_in[12];
    (void)u2b; (void)in_sizes; (void)n_in; (void)out_size;

    cudaFuncSetAttribute(k_expsum_h, cudaFuncAttributeMaxDynamicSharedMemorySize, SMEM_H);
    cudaFuncSetAttribute(k_gemm_nt3, cudaFuncAttributeMaxDynamicSharedMemorySize, SMEM_NT3);

    float* S;
    cudaGetSymbolAddress((void**)&S, g_scratch);
    float* tmp    = S + O_TMP;
    float* feat1  = S + O_FEAT1;
    float* ctx1   = S + O_CTX1;
    float* ctx2   = S + O_CTX2;
    float* qn     = S + O_QN;
    float* qkq    = S + O_QKQ;
    float* logits = S + O_LOGITS;
    float* assign = S + O_ASSIGN;
    float* aggk1  = S + O_AGGK1;
    float* aggp   = S + O_AGGP;
    float* csp    = S + O_CSP;
    float* normk  = S + O_NORMK;
    float* lpn    = S + O_LPN;
    float* lpk    = S + O_LPK;
    float* partn  = S + O_PARTN;
    float* partk  = S + O_PARTK;
    float* w1t    = S + O_W1T;
    float* w2t    = S + O_W2T;

    float* outF     = (float*)d_out;
    float* outAsg   = outF;                         // assignment [4096]
    float* feat2    = outF + NB;                    // agg_n_2 = feat2 [4096,256]
    float* aggk2    = outF + NB + (size_t)NB * DD;  // agg_k_2 [1024,256]
    float* outLoss  = outF + NB + (size_t)NB * DD + (size_t)KK * DD;

    // W transposes (once per call; cheap)
    k_transpose<<<dim3(DD/32, DIN/32), dim3(32, 8)>>>(W1, w1t, DIN, DD);
    k_transpose<<<dim3(DD/32, DIN/32), dim3(32, 8)>>>(W2, w2t, DIN, DD);

    // encoders (3xTF32 NT vs Wt) + norms
    k_gemm_nt3<<<dim3(32, 2), TPB, SMEM_NT3>>>(x1, w1t, tmp, DIN, DD);
    k_rownorm_w<<<NB/8, TPB>>>(tmp, feat1);
    k_gemm_nt3<<<dim3(32, 2), TPB, SMEM_NT3>>>(x2, w2t, tmp, DIN, DD);
    k_rownorm_w<<<NB/8, TPB>>>(tmp, feat2);
    k_rownorm_w<<<KK/8, TPB>>>(ctx1r, ctx1);
    k_rownorm_w<<<KK/8, TPB>>>(ctx2r, ctx2);
    k_rownorm_w<<<LL/8, TPB>>>(qn_r, qn);
    k_rownorm_queue_w<<<QKR/8, TPB>>>(qk_r, qnz, qkq);

    // view 1: logits (3xTF32), soft assign, hard argmax (output), agg_k_1
    k_gemm_nt3<<<dim3(32, 8), TPB, SMEM_NT3>>>(feat1, ctx1, logits, DD, KK);
    k_softmax<<<NB, TPB>>>(logits, u1a, assign);
    k_argmax<<<NB, TPB>>>(logits, u1b, outAsg);
    k_colsum_part<<<dim3(KK / TPB, CSCH), TPB>>>(assign, csp);
    k_colsum_fin<<<KK / TPB, TPB>>>(csp, normk);
    k_gemm_tn_seg<<<dim3(8, 2, NSEG), TPB>>>(assign, feat1, aggp);
    k_aggk_finish<<<KK, TPB>>>(aggp, normk, aggk1);

    // view 2
    k_gemm_nt3<<<dim3(32, 8), TPB, SMEM_NT3>>>(feat2, ctx2, logits, DD, KK);
    k_softmax<<<NB, TPB>>>(logits, u2a, assign);
    k_colsum_part<<<dim3(KK / TPB, CSCH), TPB>>>(assign, csp);
    k_colsum_fin<<<KK / TPB, TPB>>>(csp, normk);
    k_gemm_tn_seg<<<dim3(8, 2, NSEG), TPB>>>(assign, feat2, aggp);
    k_aggk_finish<<<KK, TPB>>>(aggp, normk, aggk2);

    // loss_n : negatives vs queue_n (fp16 tensor-core, fused exp-sum)
    k_expsum_h<<<dim3(NB / 128, NCHN), TPB, SMEM_H>>>(feat1, qn, partn, TPCN, NCHN);
    k_ce_row<<<NB, TPB>>>(feat1, feat2, partn, NCHN, lpn);

    // loss_k : negatives vs perturbed queue_k (fp16 tensor-core)
    k_expsum_h<<<dim3(KK / 128, NCHK), TPB, SMEM_H>>>(aggk1, qkq, partk, TPCK, NCHK);
    k_ce_row<<<KK, TPB>>>(aggk1, aggk2, partk, NCHK, lpk);

    k_loss<<<1, TPB>>>(lpn, lpk, outLoss);
}

// round 13
// speedup vs baseline: 3.3976x; 1.3987x over previous
#include <cuda_runtime.h>
#include <cuda_fp16.h>
#include <math.h>
#include <stdint.h>

#define TPB 256

// ---- problem sizes ----
constexpr int NB  = 4096;
constexpr int DIN = 1024;
constexpr int DD  = 256;
constexpr int KK  = 1024;
constexpr int LL  = 32768;
constexpr int QKR = 4096;

constexpr int NSEG = 8;
constexpr int SEGB = NB / NSEG;     // 512
constexpr int NCHN = 16, TPCN = 16;
constexpr int NCHK = 8,  TPCK = 4;
constexpr int CSCH = 32;

constexpr float INVT = 1.0f / 0.07f;

// fp16 expsum smem (uint32 words): A [128][132], B [2][128][20], red [128][4]
constexpr int ASH_W  = 128 * 132;
constexpr int BSH_W  = 2 * 128 * 20;
constexpr int REDH_W = 128 * 4;
constexpr int SMEM_H = (ASH_W + BSH_W + REDH_W) * 4;   // 90112 B -> 2 CTAs/SM

// nt3 smem
constexpr int G_CH = 128 * 36;
constexpr int SMEM_NT3 = 2 * 4 * G_CH * 4;             // 147456 B

// ---- scratch offsets (floats) ----
constexpr size_t O_TMP    = 0;
constexpr size_t O_FEAT1  = O_TMP    + (size_t)NB*DD;
constexpr size_t O_CTX1   = O_FEAT1  + (size_t)NB*DD;
constexpr size_t O_CTX2   = O_CTX1   + (size_t)KK*DD;
constexpr size_t O_LOGITS = O_CTX2   + (size_t)KK*DD;
constexpr size_t O_ASSIGN = O_LOGITS + (size_t)NB*KK;
constexpr size_t O_AGGK1  = O_ASSIGN + (size_t)NB*KK;
constexpr size_t O_AGGP   = O_AGGK1  + (size_t)KK*DD;
constexpr size_t O_CSP    = O_AGGP   + (size_t)NSEG*KK*DD;
constexpr size_t O_NORMK  = O_CSP    + (size_t)CSCH*KK;
constexpr size_t O_LPN    = O_NORMK  + KK;
constexpr size_t O_LPK    = O_LPN    + NB;
constexpr size_t O_PARTN  = O_LPK    + KK;
constexpr size_t O_PARTK  = O_PARTN  + (size_t)NB*NCHN;
constexpr size_t O_W1T    = O_PARTK  + (size_t)KK*NCHK;
constexpr size_t O_W2T    = O_W1T    + (size_t)DD*DIN;
constexpr size_t O_END    = O_W2T    + (size_t)DD*DIN;

__device__ float g_scratch[O_END];
__device__ __half g_qn_h[(size_t)LL * DD];     // queue_n, L2-normalized, half
__device__ __half g_qkq_h[(size_t)QKR * DD];   // perturbed queue_k, half

// ---------------- helpers ----------------
__device__ __forceinline__ float gumbelf(float u) {
    u = u * (1.0f - 2e-6f) + 1e-6f;
    return -logf(-logf(u));
}
__device__ __forceinline__ float gumbelf_soft(float u) {
    u = u * (1.0f - 2e-6f) + 1e-6f;
    return -__logf(-logf(u));
}

__device__ __forceinline__ uint32_t f2tf32(float x) {
    uint32_t u;
    asm("cvt.rna.tf32.f32 %0, %1;" : "=r"(u) : "f"(x));
    return u;
}

__device__ __forceinline__ uint32_t pack_h2(float a, float b) {
    __half2 h = __floats2half2_rn(a, b);
    return *(uint32_t*)&h;
}

__device__ __forceinline__ void mma_tf32(
    float& c0, float& c1, float& c2, float& c3,
    uint32_t a0, uint32_t a1, uint32_t a2, uint32_t a3,
    uint32_t b0, uint32_t b1) {
    asm volatile(
        "mma.sync.aligned.m16n8k8.row.col.f32.tf32.tf32.f32 "
        "{%0,%1,%2,%3}, {%4,%5,%6,%7}, {%8,%9}, {%0,%1,%2,%3};\n"
        : "+f"(c0), "+f"(c1), "+f"(c2), "+f"(c3)
        : "r"(a0), "r"(a1), "r"(a2), "r"(a3), "r"(b0), "r"(b1));
}

__device__ __forceinline__ void mma_f16(
    float& c0, float& c1, float& c2, float& c3,
    uint32_t a0, uint32_t a1, uint32_t a2, uint32_t a3,
    uint32_t b0, uint32_t b1) {
    asm volatile(
        "mma.sync.aligned.m16n8k16.row.col.f32.f16.f16.f32 "
        "{%0,%1,%2,%3}, {%4,%5,%6,%7}, {%8,%9}, {%0,%1,%2,%3};\n"
        : "+f"(c0), "+f"(c1), "+f"(c2), "+f"(c3)
        : "r"(a0), "r"(a1), "r"(a2), "r"(a3), "r"(b0), "r"(b1));
}

__device__ __forceinline__ float blocksum256(float v) {
    __shared__ float sh_s[8];
    #pragma unroll
    for (int o = 16; o; o >>= 1) v += __shfl_xor_sync(0xffffffffu, v, o);
    if ((threadIdx.x & 31) == 0) sh_s[threadIdx.x >> 5] = v;
    __syncthreads();
    float s = 0.f;
    #pragma unroll
    for (int i = 0; i < 8; i++) s += sh_s[i];
    __syncthreads();
    return s;
}

__device__ __forceinline__ float blockmax256(float v) {
    __shared__ float sh_m[8];
    #pragma unroll
    for (int o = 16; o; o >>= 1) v = fmaxf(v, __shfl_xor_sync(0xffffffffu, v, o));
    if ((threadIdx.x & 31) == 0) sh_m[threadIdx.x >> 5] = v;
    __syncthreads();
    float s = sh_m[0];
    #pragma unroll
    for (int i = 1; i < 8; i++) s = fmaxf(s, sh_m[i]);
    __syncthreads();
    return s;
}

// ---------- warp-per-row L2 normalize (float out) ----------
__global__ void k_rownorm_w(const float* __restrict__ src, float* __restrict__ dst) {
    int wid = threadIdx.x >> 5, lane = threadIdx.x & 31;
    int row = blockIdx.x * 8 + wid;
    const float4* s = (const float4*)(src + (size_t)row * DD);
    float4 a = s[lane], b = s[lane + 32];
    float ss = a.x*a.x + a.y*a.y + a.z*a.z + a.w*a.w
             + b.x*b.x + b.y*b.y + b.z*b.z + b.w*b.w;
    #pragma unroll
    for (int o = 16; o; o >>= 1) ss += __shfl_xor_sync(0xffffffffu, ss, o);
    float r = rsqrtf(fmaxf(ss, 1e-12f));
    float4* d = (float4*)(dst + (size_t)row * DD);
    d[lane]      = make_float4(a.x*r, a.y*r, a.z*r, a.w*r);
    d[lane + 32] = make_float4(b.x*r, b.y*r, b.z*r, b.w*r);
}

// ---------- warp-per-row L2 normalize -> HALF out (for queues) ----------
__global__ void k_rownorm_w_h(const float* __restrict__ src, __half* __restrict__ dst) {
    int wid = threadIdx.x >> 5, lane = threadIdx.x & 31;
    int row = blockIdx.x * 8 + wid;
    const float4* s = (const float4*)(src + (size_t)row * DD);
    float4 a = s[lane], b = s[lane + 32];
    float ss = a.x*a.x + a.y*a.y + a.z*a.z + a.w*a.w
             + b.x*b.x + b.y*b.y + b.z*b.z + b.w*b.w;
    #pragma unroll
    for (int o = 16; o; o >>= 1) ss += __shfl_xor_sync(0xffffffffu, ss, o);
    float r = rsqrtf(fmaxf(ss, 1e-12f));
    __half2* d = (__half2*)(dst + (size_t)row * DD);
    d[2*lane]        = __floats2half2_rn(a.x*r, a.y*r);
    d[2*lane + 1]    = __floats2half2_rn(a.z*r, a.w*r);
    d[64 + 2*lane]   = __floats2half2_rn(b.x*r, b.y*r);
    d[64 + 2*lane+1] = __floats2half2_rn(b.z*r, b.w*r);
}

// queue = l2norm(2*queue_k + qnoise) -> HALF out
__global__ void k_rownorm_queue_w_h(const float* __restrict__ qk, const float* __restrict__ nz,
                                    __half* __restrict__ dst) {
    int wid = threadIdx.x >> 5, lane = threadIdx.x & 31;
    int row = blockIdx.x * 8 + wid;
    const float4* q = (const float4*)(qk + (size_t)row * DD);
    const float4* n = (const float4*)(nz + (size_t)row * DD);
    float4 qa = q[lane], qb = q[lane + 32];
    float4 na = n[lane], nb = n[lane + 32];
    float4 a = make_float4(qa.x+na.x+qa.x, qa.y+na.y+qa.y, qa.z+na.z+qa.z, qa.w+na.w+qa.w);
    float4 b = make_float4(qb.x+nb.x+qb.x, qb.y+nb.y+qb.y, qb.z+nb.z+qb.z, qb.w+nb.w+qb.w);
    float ss = a.x*a.x + a.y*a.y + a.z*a.z + a.w*a.w
             + b.x*b.x + b.y*b.y + b.z*b.z + b.w*b.w;
    #pragma unroll
    for (int o = 16; o; o >>= 1) ss += __shfl_xor_sync(0xffffffffu, ss, o);
    float r = rsqrtf(fmaxf(ss, 1e-12f));
    __half2* d = (__half2*)(dst + (size_t)row * DD);
    d[2*lane]        = __floats2half2_rn(a.x*r, a.y*r);
    d[2*lane + 1]    = __floats2half2_rn(a.z*r, a.w*r);
    d[64 + 2*lane]   = __floats2half2_rn(b.x*r, b.y*r);
    d[64 + 2*lane+1] = __floats2half2_rn(b.z*r, b.w*r);
}

// ---------------- 32x32 tiled transpose ----------------
__global__ void k_transpose(const float* __restrict__ src, float* __restrict__ dst,
                            int R, int C) {
    __shared__ float t[32][33];
    int bx = blockIdx.x * 32, by = blockIdx.y * 32;
    int tx = threadIdx.x, ty = threadIdx.y;
    #pragma unroll
    for (int i = 0; i < 4; i++)
        t[ty + i*8][tx] = src[(size_t)(by + ty + i*8) * C + bx + tx];
    __syncthreads();
    #pragma unroll
    for (int i = 0; i < 4; i++)
        dst[(size_t)(bx + ty + i*8) * R + by + tx] = t[tx][ty + i*8];
}

// ======= 3xTF32 tensor-core GEMM NT (unchanged, validated) =======
__global__ void __launch_bounds__(TPB) k_gemm_nt3(
    const float* __restrict__ A, const float* __restrict__ B,
    float* __restrict__ C, int K, int N) {
    extern __shared__ uint32_t sm3[];
    const int tid  = threadIdx.x;
    const int lane = tid & 31;
    const int wid  = tid >> 5;
    const int g    = lane >> 2, tg = lane & 3;
    const int wm   = wid >> 2,  wn = wid & 3;
    const int m0w  = wm * 64,   n0w = wn * 32;
    const int m0   = blockIdx.x * 128, n0 = blockIdx.y * 128;
    const int KC   = K >> 5;

    float acc[4][4][4];
    #pragma unroll
    for (int i = 0; i < 4; i++)
        #pragma unroll
        for (int j = 0; j < 4; j++)
            #pragma unroll
            for (int c = 0; c < 4; c++) acc[i][j][c] = 0.f;

    #pragma unroll
    for (int it = 0; it < 4; it++) {
        int idx = it * TPB + tid;
        int r = idx >> 3, c4 = idx & 7;
        float4 qa = *(const float4*)(A + (size_t)(m0 + r) * K + c4 * 4);
        float4 qb = *(const float4*)(B + (size_t)(n0 + r) * K + c4 * 4);
        uint32_t* pah = sm3 + r * 36 + c4 * 4;
        uint32_t* pal = pah + G_CH;
        uint32_t* pbh = pah + 2 * G_CH;
        uint32_t* pbl = pah + 3 * G_CH;
        float va[4] = {qa.x, qa.y, qa.z, qa.w};
        float vb[4] = {qb.x, qb.y, qb.z, qb.w};
        #pragma unroll
        for (int c = 0; c < 4; c++) {
            uint32_t h = f2tf32(va[c]);
            pah[c] = h; pal[c] = f2tf32(va[c] - __uint_as_float(h));
            uint32_t hb = f2tf32(vb[c]);
            pbh[c] = hb; pbl[c] = f2tf32(vb[c] - __uint_as_float(hb));
        }
    }
    __syncthreads();

    int buf = 0;
    for (int kc = 0; kc < KC; kc++) {
        float4 pa[4], pb[4];
        if (kc < KC - 1) {
            int k0n = (kc + 1) * 32;
            #pragma unroll
            for (int it = 0; it < 4; it++) {
                int idx = it * TPB + tid;
                int r = idx >> 3, c4 = idx & 7;
                pa[it] = *(const float4*)(A + (size_t)(m0 + r) * K + k0n + c4 * 4);
                pb[it] = *(const float4*)(B + (size_t)(n0 + r) * K + k0n + c4 * 4);
            }
        }
        const uint32_t* AH = sm3 + buf * 4 * G_CH;
        const uint32_t* AL = AH + G_CH;
        const uint32_t* BH = AH + 2 * G_CH;
        const uint32_t* BL = AH + 3 * G_CH;
        #pragma unroll
        for (int ks = 0; ks < 4; ks++) {
            int kk = ks * 8 + tg;
            uint32_t ah[4][4], al[4][4];
            #pragma unroll
            for (int i = 0; i < 4; i++) {
                int base = (m0w + i * 16 + g) * 36;
                ah[i][0] = AH[base + kk];          ah[i][1] = AH[base + 8*36 + kk];
                ah[i][2] = AH[base + kk + 4];      ah[i][3] = AH[base + 8*36 + kk + 4];
                al[i][0] = AL[base + kk];          al[i][1] = AL[base + 8*36 + kk];
                al[i][2] = AL[base + kk + 4];      al[i][3] = AL[base + 8*36 + kk + 4];
            }
            #pragma unroll
            for (int j = 0; j < 4; j++) {
                int bbase = (n0w + j * 8 + g) * 36;
                uint32_t bh0 = BH[bbase + kk], bh1 = BH[bbase + kk + 4];
                uint32_t bl0 = BL[bbase + kk], bl1 = BL[bbase + kk + 4];
                #pragma unroll
                for (int i = 0; i < 4; i++) {
                    mma_tf32(acc[i][j][0], acc[i][j][1], acc[i][j][2], acc[i][j][3],
                             ah[i][0], ah[i][1], ah[i][2], ah[i][3], bh0, bh1);
                    mma_tf32(acc[i][j][0], acc[i][j][1], acc[i][j][2], acc[i][j][3],
                             ah[i][0], ah[i][1], ah[i][2], ah[i][3], bl0, bl1);
                    mma_tf32(acc[i][j][0], acc[i][j][1], acc[i][j][2], acc[i][j][3],
                             al[i][0], al[i][1], al[i][2], al[i][3], bh0, bh1);
                }
            }
        }
        if (kc < KC - 1) {
            uint32_t* dst = sm3 + (buf ^ 1) * 4 * G_CH;
            #pragma unroll
            for (int it = 0; it < 4; it++) {
                int idx = it * TPB + tid;
                int r = idx >> 3, c4 = idx & 7;
                uint32_t* pah = dst + r * 36 + c4 * 4;
                uint32_t* pal = pah + G_CH;
                uint32_t* pbh = pah + 2 * G_CH;
                uint32_t* pbl = pah + 3 * G_CH;
                float va[4] = {pa[it].x, pa[it].y, pa[it].z, pa[it].w};
                float vb[4] = {pb[it].x, pb[it].y, pb[it].z, pb[it].w};
                #pragma unroll
                for (int c = 0; c < 4; c++) {
                    uint32_t h = f2tf32(va[c]);
                    pah[c] = h; pal[c] = f2tf32(va[c] - __uint_as_float(h));
                    uint32_t hb = f2tf32(vb[c]);
                    pbh[c] = hb; pbl[c] = f2tf32(vb[c] - __uint_as_float(hb));
                }
            }
            __syncthreads();
            buf ^= 1;
        }
    }

    #pragma unroll
    for (int i = 0; i < 4; i++) {
        int row = m0 + m0w + i * 16 + g;
        #pragma unroll
        for (int j = 0; j < 4; j++) {
            int col = n0 + n0w + j * 8 + tg * 2;
            *(float2*)(C + (size_t)row * N + col)       = make_float2(acc[i][j][0], acc[i][j][1]);
            *(float2*)(C + (size_t)(row + 8) * N + col) = make_float2(acc[i][j][2], acc[i][j][3]);
        }
    }
}

// ====== fp16 tensor-core agg GEMM: Cpart[z] = assign[seg z]^T @ feat ======
__global__ void __launch_bounds__(TPB) k_aggk_h(
    const float* __restrict__ Asg, const float* __restrict__ Fm,
    float* __restrict__ Cpart) {
    __shared__ uint32_t Ax[128 * 20];
    __shared__ uint32_t Bx[128 * 20];
    const int tid  = threadIdx.x;
    const int lane = tid & 31;
    const int wid  = tid >> 5;
    const int g    = lane >> 2, tg = lane & 3;
    const int wm   = wid >> 2,  wn = wid & 3;
    const int m0w  = wm * 64,   n0w = wn * 32;
    const int m0   = blockIdx.x * 128;   // k-cluster
    const int n0   = blockIdx.y * 128;   // feature d
    const int z    = blockIdx.z;

    float acc[4][4][4];
    #pragma unroll
    for (int i = 0; i < 4; i++)
        #pragma unroll
        for (int j = 0; j < 4; j++)
            #pragma unroll
            for (int c = 0; c < 4; c++) acc[i][j][c] = 0.f;

    __half* Ah = (__half*)Ax;
    __half* Bh = (__half*)Bx;

    for (int c = 0; c < SEGB / 32; c++) {     // 16 chunks of 32 b
        int b0 = z * SEGB + c * 32;
        __syncthreads();                       // prior chunk mma reads done
        #pragma unroll
        for (int it = 0; it < 4; it++) {
            int idx = it * TPB + tid;
            int b = idx & 31, kg = idx >> 5;   // kg 0..31
            float4 qa = *(const float4*)(Asg + (size_t)(b0 + b) * KK + m0 + kg * 4);
            float4 qf = *(const float4*)(Fm  + (size_t)(b0 + b) * DD + n0 + kg * 4);
            Ah[(kg*4+0)*40 + b] = __float2half(qa.x);
            Ah[(kg*4+1)*40 + b] = __float2half(qa.y);
            Ah[(kg*4+2)*40 + b] = __float2half(qa.z);
            Ah[(kg*4+3)*40 + b] = __float2half(qa.w);
            Bh[(kg*4+0)*40 + b] = __float2half(qf.x);
            Bh[(kg*4+1)*40 + b] = __float2half(qf.y);
            Bh[(kg*4+2)*40 + b] = __float2half(qf.z);
            Bh[(kg*4+3)*40 + b] = __float2half(qf.w);
        }
        __syncthreads();
        #pragma unroll
        for (int kt = 0; kt < 2; kt++) {       // 2 x k16 over 32 b
            int kw = kt * 8;
            uint32_t a[4][4];
            #pragma unroll
            for (int i = 0; i < 4; i++) {
                int base = (m0w + i * 16 + g) * 20;
                a[i][0] = Ax[base + kw + tg];
                a[i][1] = Ax[base + 8*20 + kw + tg];
                a[i][2] = Ax[base + kw + 4 + tg];
                a[i][3] = Ax[base + 8*20 + kw + 4 + tg];
            }
            #pragma unroll
            for (int j = 0; j < 4; j++) {
                int bbase = (n0w + j * 8 + g) * 20;
                uint32_t b0f = Bx[bbase + kw + tg], b1f = Bx[bbase + kw + 4 + tg];
                #pragma unroll
                for (int i = 0; i < 4; i++)
                    mma_f16(acc[i][j][0], acc[i][j][1], acc[i][j][2], acc[i][j][3],
                            a[i][0], a[i][1], a[i][2], a[i][3], b0f, b1f);
            }
        }
    }

    #pragma unroll
    for (int i = 0; i < 4; i++) {
        int row = m0 + m0w + i * 16 + g;
        #pragma unroll
        for (int j = 0; j < 4; j++) {
            int col = n0 + n0w + j * 8 + tg * 2;
            float* cp = Cpart + (size_t)z * KK * DD;
            *(float2*)(cp + (size_t)row * DD + col)       = make_float2(acc[i][j][0], acc[i][j][1]);
            *(float2*)(cp + (size_t)(row + 8) * DD + col) = make_float2(acc[i][j][2], acc[i][j][3]);
        }
    }
}

// ===== fp16 tensor-core negatives GEMM + fused exp-sum; B already half =====
// FIXED: B loads use uint4 (8 halves) — uint2 (4 halves) left smem words 8-15
// unwritten, feeding garbage to the mma and NaN-ing the loss.
__global__ void __launch_bounds__(TPB) k_expsum_h(
    const float* __restrict__ Am, const __half* __restrict__ Qm,
    float* __restrict__ part, int tpc, int nch) {
    extern __shared__ uint32_t dsm[];
    uint32_t* AsU = dsm;                 // [128][132]
    uint32_t* BsU = dsm + ASH_W;         // [2][128][20]
    float*    red = (float*)(dsm + ASH_W + BSH_W);

    const int tid  = threadIdx.x;
    const int lane = tid & 31;
    const int wid  = tid >> 5;
    const int g    = lane >> 2, tg = lane & 3;
    const int wm   = wid >> 2,  wn = wid & 3;
    const int m0w  = wm * 64,   n0w = wn * 32;
    const int m0   = blockIdx.x * 128;
    const int chunk = blockIdx.y;

    #pragma unroll 8
    for (int it = 0; it < 32; it++) {
        int idx = it * TPB + tid;
        int r = idx >> 6, c4 = idx & 63;
        float4 q = *(const float4*)(Am + (size_t)(m0 + r) * DD + c4 * 4);
        uint32_t* p = AsU + r * 132 + c4 * 2;
        p[0] = pack_h2(q.x, q.y); p[1] = pack_h2(q.z, q.w);
    }

    int rA0[4], rA1[4], rB[4];
    #pragma unroll
    for (int i = 0; i < 4; i++) { rA0[i] = (m0w + i*16 + g) * 132; rA1[i] = rA0[i] + 8*132; }
    #pragma unroll
    for (int j = 0; j < 4; j++) rB[j] = (n0w + j*8 + g) * 20;

    float rp[4][2];
    #pragma unroll
    for (int i = 0; i < 4; i++) { rp[i][0] = 0.f; rp[i][1] = 0.f; }

    int buf = 0;
    __syncthreads();

    for (int t = 0; t < tpc; t++) {
        const int n0 = (chunk * tpc + t) * 128;

        __syncthreads();
        // B chunk: 128 rows x 32 halves = 4 x uint4 per row (words 0..15 all written)
        #pragma unroll
        for (int it = 0; it < 2; it++) {
            int idx = it * TPB + tid;
            int r = idx >> 2, c8 = idx & 3;
            uint4 q = *(const uint4*)(Qm + (size_t)(n0 + r) * DD + c8 * 8);
            uint32_t* p = BsU + buf * 2560 + r * 20 + c8 * 4;
            p[0] = q.x; p[1] = q.y; p[2] = q.z; p[3] = q.w;
        }
        __syncthreads();

        float acc[4][4][4];
        #pragma unroll
        for (int i = 0; i < 4; i++)
            #pragma unroll
            for (int j = 0; j < 4; j++)
                #pragma unroll
                for (int c = 0; c < 4; c++) acc[i][j][c] = 0.f;

        for (int kc = 0; kc < 8; kc++) {
            uint4 pre[2];
            if (kc < 7) {
                int k0n = (kc + 1) * 32;
                #pragma unroll
                for (int it = 0; it < 2; it++) {
                    int idx = it * TPB + tid;
                    int r = idx >> 2, c8 = idx & 3;
                    pre[it] = *(const uint4*)(Qm + (size_t)(n0 + r) * DD + k0n + c8 * 8);
                }
            }
            const uint32_t* bsb = BsU + buf * 2560;
            #pragma unroll
            for (int kt = 0; kt < 2; kt++) {
                int kw = kc * 16 + kt * 8;
                uint32_t a[4][4];
                #pragma unroll
                for (int i = 0; i < 4; i++) {
                    a[i][0] = AsU[rA0[i] + kw + tg];
                    a[i][1] = AsU[rA1[i] + kw + tg];
                    a[i][2] = AsU[rA0[i] + kw + 4 + tg];
                    a[i][3] = AsU[rA1[i] + kw + 4 + tg];
                }
                int kl = kt * 8 + tg;
                #pragma unroll
                for (int j = 0; j < 4; j++) {
                    uint32_t b0 = bsb[rB[j] + kl], b1 = bsb[rB[j] + kl + 4];
                    #pragma unroll
                    for (int i = 0; i < 4; i++)
                        mma_f16(acc[i][j][0], acc[i][j][1], acc[i][j][2], acc[i][j][3],
                                a[i][0], a[i][1], a[i][2], a[i][3], b0, b1);
                }
            }
            if (kc < 7) {
                #pragma unroll
                for (int it = 0; it < 2; it++) {
                    int idx = it * TPB + tid;
                    int r = idx >> 2, c8 = idx & 3;
                    uint32_t* p = BsU + (buf ^ 1) * 2560 + r * 20 + c8 * 4;
                    p[0] = pre[it].x; p[1] = pre[it].y; p[2] = pre[it].z; p[3] = pre[it].w;
                }
                __syncthreads();
                buf ^= 1;
            }
        }

        #pragma unroll
        for (int i = 0; i < 4; i++) {
            float s0 = 0.f, s1 = 0.f;
            #pragma unroll
            for (int j = 0; j < 4; j++) {
                s0 += __expf(acc[i][j][0] * INVT - INVT) + __expf(acc[i][j][1] * INVT - INVT);
                s1 += __expf(acc[i][j][2] * INVT - INVT) + __expf(acc[i][j][3] * INVT - INVT);
            }
            rp[i][0] += s0; rp[i][1] += s1;
        }
    }

    #pragma unroll
    for (int i = 0; i < 4; i++)
        #pragma unroll
        for (int h = 0; h < 2; h++) {
            float v = rp[i][h];
            v += __shfl_xor_sync(0xffffffffu, v, 1);
            v += __shfl_xor_sync(0xffffffffu, v, 2);
            if (tg == 0) red[(m0w + i*16 + h*8 + g) * 4 + wn] = v;
        }
    __syncthreads();
    if (tid < 128) {
        float s = red[tid*4+0] + red[tid*4+1] + red[tid*4+2] + red[tid*4+3];
        part[(size_t)(m0 + tid) * nch + chunk] = s;
    }
}

// ------- merged soft-assign + hard-argmax (view 1): one logits pass -------
__global__ void k_assign(const float* __restrict__ logits,
                         const float* __restrict__ u_soft, const float* __restrict__ u_hard,
                         float* __restrict__ assign, float* __restrict__ outAsg) {
    __shared__ float sb[8]; __shared__ int si[8];
    int r = blockIdx.x, t = threadIdx.x;
    float zs[4], best = -1e30f; int bi = 0;
    #pragma unroll
    for (int j = 0; j < 4; j++) {
        int k = j * 256 + t;
        size_t i = (size_t)r * KK + k;
        float lg = logits[i];
        zs[j] = (lg + gumbelf_soft(u_soft[i])) * 2.0f;
        float zh = lg + gumbelf(u_hard[i]);
        if (zh > best) { best = zh; bi = k; }
    }
    float m = fmaxf(fmaxf(zs[0], zs[1]), fmaxf(zs[2], zs[3]));
    m = blockmax256(m);
    float s = 0.f;
    #pragma unroll
    for (int j = 0; j < 4; j++) { zs[j] = __expf(zs[j] - m); s += zs[j]; }
    s = blocksum256(s);
    float inv = 1.0f / s;
    #pragma unroll
    for (int j = 0; j < 4; j++)
        assign[(size_t)r * KK + j * 256 + t] = zs[j] * inv;
    #pragma unroll
    for (int o = 16; o; o >>= 1) {
        float ob = __shfl_xor_sync(0xffffffffu, best, o);
        int   oi = __shfl_xor_sync(0xffffffffu, bi, o);
        if (ob > best || (ob == best && oi < bi)) { best = ob; bi = oi; }
    }
    if ((t & 31) == 0) { sb[t >> 5] = best; si[t >> 5] = bi; }
    __syncthreads();
    if (t == 0) {
        #pragma unroll
        for (int w = 1; w < 8; w++)
            if (sb[w] > best || (sb[w] == best && si[w] < bi)) { best = sb[w]; bi = si[w]; }
        outAsg[r] = (float)bi;
    }
}

// ---------------- gumbel softmax (soft only, view 2) ----------------
__global__ void k_softmax(const float* __restrict__ logits, const float* __restrict__ u,
                          float* __restrict__ assign) {
    int r = blockIdx.x, t = threadIdx.x;
    float z[4];
    #pragma unroll
    for (int j = 0; j < 4; j++) {
        int k = j * 256 + t;
        size_t i = (size_t)r * KK + k;
        z[j] = (logits[i] + gumbelf_soft(u[i])) * 2.0f;
    }
    float m = fmaxf(fmaxf(z[0], z[1]), fmaxf(z[2], z[3]));
    m = blockmax256(m);
    float s = 0.f;
    #pragma unroll
    for (int j = 0; j < 4; j++) { z[j] = __expf(z[j] - m); s += z[j]; }
    s = blocksum256(s);
    float inv = 1.0f / s;
    #pragma unroll
    for (int j = 0; j < 4; j++)
        assign[(size_t)r * KK + j * 256 + t] = z[j] * inv;
}

// ---------------- column sums of assign (fp32 normalizer) ----------------
__global__ void k_colsum_part(const float* __restrict__ assign, float* __restrict__ csp) {
    int k = blockIdx.x * TPB + threadIdx.x;
    int c = blockIdx.y;
    float s = 0.f;
    #pragma unroll 4
    for (int b = c * (NB / CSCH); b < (c + 1) * (NB / CSCH); b++)
        s += assign[(size_t)b * KK + k];
    csp[(size_t)c * KK + k] = s;
}
__global__ void k_colsum_fin(const float* __restrict__ csp, float* __restrict__ norm) {
    int k = blockIdx.x * TPB + threadIdx.x;
    float s = 0.f;
    #pragma unroll
    for (int c = 0; c < CSCH; c++) s += csp[(size_t)c * KK + k];
    norm[k] = s;
}

// ---------------- agg_k finish ----------------
__global__ void k_aggk_finish(const float* __restrict__ part, const float* __restrict__ norm,
                              float* __restrict__ dst) {
    int r = blockIdx.x, t = threadIdx.x;
    float v = 0.f;
    #pragma unroll
    for (int s = 0; s < NSEG; s++) v += part[(size_t)s * KK * DD + (size_t)r * DD + t];
    v = v / (norm[r] + 1e-8f);
    float ss = blocksum256(v * v);
    dst[(size_t)r * DD + t] = v * rsqrtf(fmaxf(ss, 1e-12f));
}

// ------------- per-row CE -------------
__global__ void k_ce_row(const float* __restrict__ q, const float* __restrict__ kv,
                         const float* __restrict__ part, int nch,
                         float* __restrict__ lp) {
    int r = blockIdx.x, t = threadIdx.x;
    float v = q[(size_t)r * DD + t] * kv[(size_t)r * DD + t];
    float lpos = blocksum256(v);
    if (t == 0) {
        float S = expf(lpos * INVT - INVT);
        for (int c = 0; c < nch; c++) S += part[(size_t)r * nch + c];
        lp[r] = lpos * INVT - INVT - logf(S);
    }
}

// ---------------- final scalar loss ----------------
__global__ void k_loss(const float* __restrict__ lpn, const float* __restrict__ lpk,
                       float* __restrict__ out) {
    int t = threadIdx.x;
    float s1 = 0.f;
    for (int i = t; i < NB; i += TPB) s1 += lpn[i];
    s1 = blocksum256(s1);
    float s2 = 0.f;
    for (int i = t; i < KK; i += TPB) s2 += lpk[i];
    s2 = blocksum256(s2);
    if (t == 0) out[0] = -(s1 / NB) - (s2 / KK);
}

// ============================ launcher ============================
extern "C" void kernel_launch(void* const* d_in, const int* in_sizes, int n_in,
                              void* d_out, int out_size) {
    const float* x1    = (const float*)d_in[0];
    const float* x2    = (const float*)d_in[1];
    const float* W1    = (const float*)d_in[2];
    const float* W2    = (const float*)d_in[3];
    const float* ctx1r = (const float*)d_in[4];
    const float* ctx2r = (const float*)d_in[5];
    const float* qn_r  = (const float*)d_in[6];
    const float* qk_r  = (const float*)d_in[7];
    const float* u1a   = (const float*)d_in[8];
    const float* u1b   = (const float*)d_in[9];
    const float* u2a   = (const float*)d_in[10];
    const float* u2b   = (const float*)d_in[11];
    const float* qnz   = (const float*)d_in[12];
    (void)u2b; (void)in_sizes; (void)n_in; (void)out_size;

    cudaFuncSetAttribute(k_expsum_h, cudaFuncAttributeMaxDynamicSharedMemorySize, SMEM_H);
    cudaFuncSetAttribute(k_gemm_nt3, cudaFuncAttributeMaxDynamicSharedMemorySize, SMEM_NT3);

    float* S;
    cudaGetSymbolAddress((void**)&S, g_scratch);
    __half* qn_h;  cudaGetSymbolAddress((void**)&qn_h,  g_qn_h);
    __half* qkq_h; cudaGetSymbolAddress((void**)&qkq_h, g_qkq_h);

    float* tmp    = S + O_TMP;
    float* feat1  = S + O_FEAT1;
    float* ctx1   = S + O_CTX1;
    float* ctx2   = S + O_CTX2;
    float* logits = S + O_LOGITS;
    float* assign = S + O_ASSIGN;
    float* aggk1  = S + O_AGGK1;
    float* aggp   = S + O_AGGP;
    float* csp    = S + O_CSP;
    float* normk  = S + O_NORMK;
    float* lpn    = S + O_LPN;
    float* lpk    = S + O_LPK;
    float* partn  = S + O_PARTN;
    float* partk  = S + O_PARTK;
    float* w1t    = S + O_W1T;
    float* w2t    = S + O_W2T;

    float* outF     = (float*)d_out;
    float* outAsg   = outF;
    float* feat2    = outF + NB;
    float* aggk2    = outF + NB + (size_t)NB * DD;
    float* outLoss  = outF + NB + (size_t)NB * DD + (size_t)KK * DD;

    k_transpose<<<dim3(DD/32, DIN/32), dim3(32, 8)>>>(W1, w1t, DIN, DD);
    k_transpose<<<dim3(DD/32, DIN/32), dim3(32, 8)>>>(W2, w2t, DIN, DD);

    k_gemm_nt3<<<dim3(32, 2), TPB, SMEM_NT3>>>(x1, w1t, tmp, DIN, DD);
    k_rownorm_w<<<NB/8, TPB>>>(tmp, feat1);
    k_gemm_nt3<<<dim3(32, 2), TPB, SMEM_NT3>>>(x2, w2t, tmp, DIN, DD);
    k_rownorm_w<<<NB/8, TPB>>>(tmp, feat2);
    k_rownorm_w<<<KK/8, TPB>>>(ctx1r, ctx1);
    k_rownorm_w<<<KK/8, TPB>>>(ctx2r, ctx2);
    k_rownorm_w_h<<<LL/8, TPB>>>(qn_r, qn_h);
    k_rownorm_queue_w_h<<<QKR/8, TPB>>>(qk_r, qnz, qkq_h);

    // view 1
    k_gemm_nt3<<<dim3(32, 8), TPB, SMEM_NT3>>>(feat1, ctx1, logits, DD, KK);
    k_assign<<<NB, TPB>>>(logits, u1a, u1b, assign, outAsg);
    k_colsum_part<<<dim3(KK / TPB, CSCH), TPB>>>(assign, csp);
    k_colsum_fin<<<KK / TPB, TPB>>>(csp, normk);
    k_aggk_h<<<dim3(8, 2, NSEG), TPB>>>(assign, feat1, aggp);
    k_aggk_finish<<<KK, TPB>>>(aggp, normk, aggk1);

    // view 2
    k_gemm_nt3<<<dim3(32, 8), TPB, SMEM_NT3>>>(feat2, ctx2, logits, DD, KK);
    k_softmax<<<NB, TPB>>>(logits, u2a, assign);
    k_colsum_part<<<dim3(KK / TPB, CSCH), TPB>>>(assign, csp);
    k_colsum_fin<<<KK / TPB, TPB>>>(csp, normk);
    k_aggk_h<<<dim3(8, 2, NSEG), TPB>>>(assign, feat2, aggp);
    k_aggk_finish<<<KK, TPB>>>(aggp, normk, aggk2);

    // losses
    k_expsum_h<<<dim3(NB / 128, NCHN), TPB, SMEM_H>>>(feat1, qn_h, partn, TPCN, NCHN);
    k_ce_row<<<NB, TPB>>>(feat1, feat2, partn, NCHN, lpn);
    k_expsum_h<<<dim3(KK / 128, NCHK), TPB, SMEM_H>>>(aggk1, qkq_h, partk, TPCK, NCHK);
    k_ce_row<<<KK, TPB>>>(aggk1, aggk2, partk, NCHK, lpk);

    k_loss<<<1, TPB>>>(lpn, lpk, outLoss);
}

// round 17
// speedup vs baseline: 3.9017x; 1.1484x over previous
#include <cuda_runtime.h>
#include <cuda_fp16.h>
#include <math.h>
#include <stdint.h>

#define TPB 256

// ---- problem sizes ----
constexpr int NB  = 4096;
constexpr int DIN = 1024;
constexpr int DD  = 256;
constexpr int KK  = 1024;
constexpr int LL  = 32768;
constexpr int QKR = 4096;

constexpr int NSEG = 8;
constexpr int SEGB = NB / NSEG;     // 512
constexpr int NCHN = 16, TPCN = 16;
constexpr int NCHK = 8,  TPCK = 4;
constexpr int CSCH = 32;

constexpr float INVT = 1.0f / 0.07f;

// fp16 expsum smem (uint32 words): A [128][132], B [2][128][20], red [128][4]
constexpr int ASH_W  = 128 * 132;
constexpr int BSH_W  = 2 * 128 * 20;
constexpr int REDH_W = 128 * 4;
constexpr int SMEM_H = (ASH_W + BSH_W + REDH_W) * 4;   // 90112 B -> 2 CTAs/SM

// fp16-split GEMM smem: 2 bufs x (AH, AL, BH, BL) each 128x20 words
constexpr int GH_CH = 128 * 20;
constexpr int SMEM_NTH = 2 * 4 * GH_CH * 4;            // 81920 B -> 2 CTAs/SM

// ---- scratch offsets (floats) ----
constexpr size_t O_TMP    = 0;
constexpr size_t O_FEAT1  = O_TMP    + (size_t)NB*DD;
constexpr size_t O_CTX1   = O_FEAT1  + (size_t)NB*DD;
constexpr size_t O_CTX2   = O_CTX1   + (size_t)KK*DD;
constexpr size_t O_LOGITS = O_CTX2   + (size_t)KK*DD;
constexpr size_t O_ASSIGN = O_LOGITS + (size_t)NB*KK;
constexpr size_t O_AGGK1  = O_ASSIGN + (size_t)NB*KK;
constexpr size_t O_AGGP   = O_AGGK1  + (size_t)KK*DD;
constexpr size_t O_CSP    = O_AGGP   + (size_t)NSEG*KK*DD;
constexpr size_t O_NORMK  = O_CSP    + (size_t)CSCH*KK;
constexpr size_t O_LPN    = O_NORMK  + KK;
constexpr size_t O_LPK    = O_LPN    + NB;
constexpr size_t O_PARTN  = O_LPK    + KK;
constexpr size_t O_PARTK  = O_PARTN  + (size_t)NB*NCHN;
constexpr size_t O_W1T    = O_PARTK  + (size_t)KK*NCHK;
constexpr size_t O_W2T    = O_W1T    + (size_t)DD*DIN;
constexpr size_t O_END    = O_W2T    + (size_t)DD*DIN;

__device__ float g_scratch[O_END];
__device__ __half g_qn_h[(size_t)LL * DD];
__device__ __half g_qkq_h[(size_t)QKR * DD];

// ---------------- helpers ----------------
__device__ __forceinline__ float gumbelf(float u) {
    u = u * (1.0f - 2e-6f) + 1e-6f;
    return -logf(-logf(u));
}
__device__ __forceinline__ float gumbelf_soft(float u) {
    u = u * (1.0f - 2e-6f) + 1e-6f;
    return -__logf(-logf(u));
}

__device__ __forceinline__ uint32_t pack_h2(float a, float b) {
    __half2 h = __floats2half2_rn(a, b);
    return *(uint32_t*)&h;
}

// hi/lo fp16 split of two floats -> packed hi word + lo word
__device__ __forceinline__ void split2(float a, float b, uint32_t& hw, uint32_t& lw) {
    __half ha = __float2half(a), hb = __float2half(b);
    __half la = __float2half(a - __half2float(ha));
    __half lb = __float2half(b - __half2float(hb));
    __half2 h2 = __halves2half2(ha, hb); hw = *(uint32_t*)&h2;
    __half2 l2 = __halves2half2(la, lb); lw = *(uint32_t*)&l2;
}

__device__ __forceinline__ void mma_f16(
    float& c0, float& c1, float& c2, float& c3,
    uint32_t a0, uint32_t a1, uint32_t a2, uint32_t a3,
    uint32_t b0, uint32_t b1) {
    asm volatile(
        "mma.sync.aligned.m16n8k16.row.col.f32.f16.f16.f32 "
        "{%0,%1,%2,%3}, {%4,%5,%6,%7}, {%8,%9}, {%0,%1,%2,%3};\n"
        : "+f"(c0), "+f"(c1), "+f"(c2), "+f"(c3)
        : "r"(a0), "r"(a1), "r"(a2), "r"(a3), "r"(b0), "r"(b1));
}

__device__ __forceinline__ float blocksum256(float v) {
    __shared__ float sh_s[8];
    #pragma unroll
    for (int o = 16; o; o >>= 1) v += __shfl_xor_sync(0xffffffffu, v, o);
    if ((threadIdx.x & 31) == 0) sh_s[threadIdx.x >> 5] = v;
    __syncthreads();
    float s = 0.f;
    #pragma unroll
    for (int i = 0; i < 8; i++) s += sh_s[i];
    __syncthreads();
    return s;
}

__device__ __forceinline__ float blockmax256(float v) {
    __shared__ float sh_m[8];
    #pragma unroll
    for (int o = 16; o; o >>= 1) v = fmaxf(v, __shfl_xor_sync(0xffffffffu, v, o));
    if ((threadIdx.x & 31) == 0) sh_m[threadIdx.x >> 5] = v;
    __syncthreads();
    float s = sh_m[0];
    #pragma unroll
    for (int i = 1; i < 8; i++) s = fmaxf(s, sh_m[i]);
    __syncthreads();
    return s;
}

// ---------- warp-per-row L2 normalize (float out) ----------
__global__ void k_rownorm_w(const float* __restrict__ src, float* __restrict__ dst) {
    int wid = threadIdx.x >> 5, lane = threadIdx.x & 31;
    int row = blockIdx.x * 8 + wid;
    const float4* s = (const float4*)(src + (size_t)row * DD);
    float4 a = s[lane], b = s[lane + 32];
    float ss = a.x*a.x + a.y*a.y + a.z*a.z + a.w*a.w
             + b.x*b.x + b.y*b.y + b.z*b.z + b.w*b.w;
    #pragma unroll
    for (int o = 16; o; o >>= 1) ss += __shfl_xor_sync(0xffffffffu, ss, o);
    float r = rsqrtf(fmaxf(ss, 1e-12f));
    float4* d = (float4*)(dst + (size_t)row * DD);
    d[lane]      = make_float4(a.x*r, a.y*r, a.z*r, a.w*r);
    d[lane + 32] = make_float4(b.x*r, b.y*r, b.z*r, b.w*r);
}

// ---------- warp-per-row L2 normalize -> HALF out (for queues) ----------
__global__ void k_rownorm_w_h(const float* __restrict__ src, __half* __restrict__ dst) {
    int wid = threadIdx.x >> 5, lane = threadIdx.x & 31;
    int row = blockIdx.x * 8 + wid;
    const float4* s = (const float4*)(src + (size_t)row * DD);
    float4 a = s[lane], b = s[lane + 32];
    float ss = a.x*a.x + a.y*a.y + a.z*a.z + a.w*a.w
             + b.x*b.x + b.y*b.y + b.z*b.z + b.w*b.w;
    #pragma unroll
    for (int o = 16; o; o >>= 1) ss += __shfl_xor_sync(0xffffffffu, ss, o);
    float r = rsqrtf(fmaxf(ss, 1e-12f));
    __half2* d = (__half2*)(dst + (size_t)row * DD);
    d[2*lane]        = __floats2half2_rn(a.x*r, a.y*r);
    d[2*lane + 1]    = __floats2half2_rn(a.z*r, a.w*r);
    d[64 + 2*lane]   = __floats2half2_rn(b.x*r, b.y*r);
    d[64 + 2*lane+1] = __floats2half2_rn(b.z*r, b.w*r);
}

// queue = l2norm(2*queue_k + qnoise) -> HALF out
__global__ void k_rownorm_queue_w_h(const float* __restrict__ qk, const float* __restrict__ nz,
                                    __half* __restrict__ dst) {
    int wid = threadIdx.x >> 5, lane = threadIdx.x & 31;
    int row = blockIdx.x * 8 + wid;
    const float4* q = (const float4*)(qk + (size_t)row * DD);
    const float4* n = (const float4*)(nz + (size_t)row * DD);
    float4 qa = q[lane], qb = q[lane + 32];
    float4 na = n[lane], nb = n[lane + 32];
    float4 a = make_float4(qa.x+na.x+qa.x, qa.y+na.y+qa.y, qa.z+na.z+qa.z, qa.w+na.w+qa.w);
    float4 b = make_float4(qb.x+nb.x+qb.x, qb.y+nb.y+qb.y, qb.z+nb.z+qb.z, qb.w+nb.w+qb.w);
    float ss = a.x*a.x + a.y*a.y + a.z*a.z + a.w*a.w
             + b.x*b.x + b.y*b.y + b.z*b.z + b.w*b.w;
    #pragma unroll
    for (int o = 16; o; o >>= 1) ss += __shfl_xor_sync(0xffffffffu, ss, o);
    float r = rsqrtf(fmaxf(ss, 1e-12f));
    __half2* d = (__half2*)(dst + (size_t)row * DD);
    d[2*lane]        = __floats2half2_rn(a.x*r, a.y*r);
    d[2*lane + 1]    = __floats2half2_rn(a.z*r, a.w*r);
    d[64 + 2*lane]   = __floats2half2_rn(b.x*r, b.y*r);
    d[64 + 2*lane+1] = __floats2half2_rn(b.z*r, b.w*r);
}

// ---------------- 32x32 tiled transpose ----------------
__global__ void k_transpose(const float* __restrict__ src, float* __restrict__ dst,
                            int R, int C) {
    __shared__ float t[32][33];
    int bx = blockIdx.x * 32, by = blockIdx.y * 32;
    int tx = threadIdx.x, ty = threadIdx.y;
    #pragma unroll
    for (int i = 0; i < 4; i++)
        t[ty + i*8][tx] = src[(size_t)(by + ty + i*8) * C + bx + tx];
    __syncthreads();
    #pragma unroll
    for (int i = 0; i < 4; i++)
        dst[(size_t)(bx + ty + i*8) * R + by + tx] = t[tx][ty + i*8];
}

// ==== fp16-split tensor-core GEMM NT: C[M,N] = A[M,K] @ B[N,K]^T ====
// hi/lo split: C = AH*BH + AH*BL + AL*BH (error ~2^-22, fp32-grade).
__global__ void __launch_bounds__(TPB) k_gemm_nth(
    const float* __restrict__ A, const float* __restrict__ B,
    float* __restrict__ C, int K, int N) {
    extern __shared__ uint32_t smh[];
    const int tid  = threadIdx.x;
    const int lane = tid & 31;
    const int wid  = tid >> 5;
    const int g    = lane >> 2, tg = lane & 3;
    const int wm   = wid >> 2,  wn = wid & 3;
    const int m0w  = wm * 64,   n0w = wn * 32;
    const int m0   = blockIdx.x * 128, n0 = blockIdx.y * 128;
    const int KC   = K >> 5;

    float acc[4][4][4];
    #pragma unroll
    for (int i = 0; i < 4; i++)
        #pragma unroll
        for (int j = 0; j < 4; j++)
            #pragma unroll
            for (int c = 0; c < 4; c++) acc[i][j][c] = 0.f;

    #pragma unroll
    for (int it = 0; it < 4; it++) {
        int idx = it * TPB + tid;
        int r = idx >> 3, c4 = idx & 7;
        float4 qa = *(const float4*)(A + (size_t)(m0 + r) * K + c4 * 4);
        float4 qb = *(const float4*)(B + (size_t)(n0 + r) * K + c4 * 4);
        uint32_t* pAH = smh + r * 20 + c4 * 2;
        uint32_t* pAL = pAH + GH_CH;
        uint32_t* pBH = pAH + 2 * GH_CH;
        uint32_t* pBL = pAH + 3 * GH_CH;
        uint32_t hw, lw;
        split2(qa.x, qa.y, hw, lw); pAH[0] = hw; pAL[0] = lw;
        split2(qa.z, qa.w, hw, lw); pAH[1] = hw; pAL[1] = lw;
        split2(qb.x, qb.y, hw, lw); pBH[0] = hw; pBL[0] = lw;
        split2(qb.z, qb.w, hw, lw); pBH[1] = hw; pBL[1] = lw;
    }
    __syncthreads();

    int buf = 0;
    for (int kc = 0; kc < KC; kc++) {
        float4 pa[4], pb[4];
        if (kc < KC - 1) {
            int k0n = (kc + 1) * 32;
            #pragma unroll
            for (int it = 0; it < 4; it++) {
                int idx = it * TPB + tid;
                int r = idx >> 3, c4 = idx & 7;
                pa[it] = *(const float4*)(A + (size_t)(m0 + r) * K + k0n + c4 * 4);
                pb[it] = *(const float4*)(B + (size_t)(n0 + r) * K + k0n + c4 * 4);
            }
        }
        const uint32_t* AH = smh + buf * 4 * GH_CH;
        const uint32_t* AL = AH + GH_CH;
        const uint32_t* BH = AH + 2 * GH_CH;
        const uint32_t* BL = AH + 3 * GH_CH;
        #pragma unroll
        for (int kt = 0; kt < 2; kt++) {
            int kw = kt * 8;
            uint32_t ah[4][4], al[4][4];
            #pragma unroll
            for (int i = 0; i < 4; i++) {
                int base = (m0w + i * 16 + g) * 20;
                ah[i][0] = AH[base + kw + tg];
                ah[i][1] = AH[base + 8*20 + kw + tg];
                ah[i][2] = AH[base + kw + 4 + tg];
                ah[i][3] = AH[base + 8*20 + kw + 4 + tg];
                al[i][0] = AL[base + kw + tg];
                al[i][1] = AL[base + 8*20 + kw + tg];
                al[i][2] = AL[base + kw + 4 + tg];
                al[i][3] = AL[base + 8*20 + kw + 4 + tg];
            }
            #pragma unroll
            for (int j = 0; j < 4; j++) {
                int bbase = (n0w + j * 8 + g) * 20;
                uint32_t bh0 = BH[bbase + kw + tg], bh1 = BH[bbase + kw + 4 + tg];
                uint32_t bl0 = BL[bbase + kw + tg], bl1 = BL[bbase + kw + 4 + tg];
                #pragma unroll
                for (int i = 0; i < 4; i++) {
                    mma_f16(acc[i][j][0], acc[i][j][1], acc[i][j][2], acc[i][j][3],
                            ah[i][0], ah[i][1], ah[i][2], ah[i][3], bh0, bh1);
                    mma_f16(acc[i][j][0], acc[i][j][1], acc[i][j][2], acc[i][j][3],
                            ah[i][0], ah[i][1], ah[i][2], ah[i][3], bl0, bl1);
                    mma_f16(acc[i][j][0], acc[i][j][1], acc[i][j][2], acc[i][j][3],
                            al[i][0], al[i][1], al[i][2], al[i][3], bh0, bh1);
                }
            }
        }
        if (kc < KC - 1) {
            uint32_t* dst = smh + (buf ^ 1) * 4 * GH_CH;
            #pragma unroll
            for (int it = 0; it < 4; it++) {
                int idx = it * TPB + tid;
                int r = idx >> 3, c4 = idx & 7;
                uint32_t* pAH = dst + r * 20 + c4 * 2;
                uint32_t* pAL = pAH + GH_CH;
                uint32_t* pBH = pAH + 2 * GH_CH;
                uint32_t* pBL = pAH + 3 * GH_CH;
                uint32_t hw, lw;
                split2(pa[it].x, pa[it].y, hw, lw); pAH[0] = hw; pAL[0] = lw;
                split2(pa[it].z, pa[it].w, hw, lw); pAH[1] = hw; pAL[1] = lw;
                split2(pb[it].x, pb[it].y, hw, lw); pBH[0] = hw; pBL[0] = lw;
                split2(pb[it].z, pb[it].w, hw, lw); pBH[1] = hw; pBL[1] = lw;
            }
            __syncthreads();
            buf ^= 1;
        }
    }

    #pragma unroll
    for (int i = 0; i < 4; i++) {
        int row = m0 + m0w + i * 16 + g;
        #pragma unroll
        for (int j = 0; j < 4; j++) {
            int col = n0 + n0w + j * 8 + tg * 2;
            *(float2*)(C + (size_t)row * N + col)       = make_float2(acc[i][j][0], acc[i][j][1]);
            *(float2*)(C + (size_t)(row + 8) * N + col) = make_float2(acc[i][j][2], acc[i][j][3]);
        }
    }
}

// ====== fp16 tensor-core agg GEMM: Cpart[z] = assign[seg z]^T @ feat ======
__global__ void __launch_bounds__(TPB) k_aggk_h(
    const float* __restrict__ Asg, const float* __restrict__ Fm,
    float* __restrict__ Cpart) {
    __shared__ uint32_t Ax[128 * 20];
    __shared__ uint32_t Bx[128 * 20];
    const int tid  = threadIdx.x;
    const int lane = tid & 31;
    const int wid  = tid >> 5;
    const int g    = lane >> 2, tg = lane & 3;
    const int wm   = wid >> 2,  wn = wid & 3;
    const int m0w  = wm * 64,   n0w = wn * 32;
    const int m0   = blockIdx.x * 128;
    const int n0   = blockIdx.y * 128;
    const int z    = blockIdx.z;

    float acc[4][4][4];
    #pragma unroll
    for (int i = 0; i < 4; i++)
        #pragma unroll
        for (int j = 0; j < 4; j++)
            #pragma unroll
            for (int c = 0; c < 4; c++) acc[i][j][c] = 0.f;

    __half* Ah = (__half*)Ax;
    __half* Bh = (__half*)Bx;

    for (int c = 0; c < SEGB / 32; c++) {
        int b0 = z * SEGB + c * 32;
        __syncthreads();
        #pragma unroll
        for (int it = 0; it < 4; it++) {
            int idx = it * TPB + tid;
            int b = idx & 31, kg = idx >> 5;
            float4 qa = *(const float4*)(Asg + (size_t)(b0 + b) * KK + m0 + kg * 4);
            float4 qf = *(const float4*)(Fm  + (size_t)(b0 + b) * DD + n0 + kg * 4);
            Ah[(kg*4+0)*40 + b] = __float2half(qa.x);
            Ah[(kg*4+1)*40 + b] = __float2half(qa.y);
            Ah[(kg*4+2)*40 + b] = __float2half(qa.z);
            Ah[(kg*4+3)*40 + b] = __float2half(qa.w);
            Bh[(kg*4+0)*40 + b] = __float2half(qf.x);
            Bh[(kg*4+1)*40 + b] = __float2half(qf.y);
            Bh[(kg*4+2)*40 + b] = __float2half(qf.z);
            Bh[(kg*4+3)*40 + b] = __float2half(qf.w);
        }
        __syncthreads();
        #pragma unroll
        for (int kt = 0; kt < 2; kt++) {
            int kw = kt * 8;
            uint32_t a[4][4];
            #pragma unroll
            for (int i = 0; i < 4; i++) {
                int base = (m0w + i * 16 + g) * 20;
                a[i][0] = Ax[base + kw + tg];
                a[i][1] = Ax[base + 8*20 + kw + tg];
                a[i][2] = Ax[base + kw + 4 + tg];
                a[i][3] = Ax[base + 8*20 + kw + 4 + tg];
            }
            #pragma unroll
            for (int j = 0; j < 4; j++) {
                int bbase = (n0w + j * 8 + g) * 20;
                uint32_t b0f = Bx[bbase + kw + tg], b1f = Bx[bbase + kw + 4 + tg];
                #pragma unroll
                for (int i = 0; i < 4; i++)
                    mma_f16(acc[i][j][0], acc[i][j][1], acc[i][j][2], acc[i][j][3],
                            a[i][0], a[i][1], a[i][2], a[i][3], b0f, b1f);
            }
        }
    }

    #pragma unroll
    for (int i = 0; i < 4; i++) {
        int row = m0 + m0w + i * 16 + g;
        #pragma unroll
        for (int j = 0; j < 4; j++) {
            int col = n0 + n0w + j * 8 + tg * 2;
            float* cp = Cpart + (size_t)z * KK * DD;
            *(float2*)(cp + (size_t)row * DD + col)       = make_float2(acc[i][j][0], acc[i][j][1]);
            *(float2*)(cp + (size_t)(row + 8) * DD + col) = make_float2(acc[i][j][2], acc[i][j][3]);
        }
    }
}

// ===== fp16 tensor-core negatives GEMM + fused exp-sum; B half (uint4 feed) =====
__global__ void __launch_bounds__(TPB) k_expsum_h(
    const float* __restrict__ Am, const __half* __restrict__ Qm,
    float* __restrict__ part, int tpc, int nch) {
    extern __shared__ uint32_t dsm[];
    uint32_t* AsU = dsm;                 // [128][132]
    uint32_t* BsU = dsm + ASH_W;         // [2][128][20]
    float*    red = (float*)(dsm + ASH_W + BSH_W);

    const int tid  = threadIdx.x;
    const int lane = tid & 31;
    const int wid  = tid >> 5;
    const int g    = lane >> 2, tg = lane & 3;
    const int wm   = wid >> 2,  wn = wid & 3;
    const int m0w  = wm * 64,   n0w = wn * 32;
    const int m0   = blockIdx.x * 128;
    const int chunk = blockIdx.y;

    #pragma unroll 8
    for (int it = 0; it < 32; it++) {
        int idx = it * TPB + tid;
        int r = idx >> 6, c4 = idx & 63;
        float4 q = *(const float4*)(Am + (size_t)(m0 + r) * DD + c4 * 4);
        uint32_t* p = AsU + r * 132 + c4 * 2;
        p[0] = pack_h2(q.x, q.y); p[1] = pack_h2(q.z, q.w);
    }

    int rA0[4], rA1[4], rB[4];
    #pragma unroll
    for (int i = 0; i < 4; i++) { rA0[i] = (m0w + i*16 + g) * 132; rA1[i] = rA0[i] + 8*132; }
    #pragma unroll
    for (int j = 0; j < 4; j++) rB[j] = (n0w + j*8 + g) * 20;

    float rp[4][2];
    #pragma unroll
    for (int i = 0; i < 4; i++) { rp[i][0] = 0.f; rp[i][1] = 0.f; }

    int buf = 0;
    __syncthreads();

    for (int t = 0; t < tpc; t++) {
        const int n0 = (chunk * tpc + t) * 128;

        __syncthreads();
        #pragma unroll
        for (int it = 0; it < 2; it++) {
            int idx = it * TPB + tid;
            int r = idx >> 2, c8 = idx & 3;
            uint4 q = *(const uint4*)(Qm + (size_t)(n0 + r) * DD + c8 * 8);
            uint32_t* p = BsU + buf * 2560 + r * 20 + c8 * 4;
            p[0] = q.x; p[1] = q.y; p[2] = q.z; p[3] = q.w;
        }
        __syncthreads();

        float acc[4][4][4];
        #pragma unroll
        for (int i = 0; i < 4; i++)
            #pragma unroll
            for (int j = 0; j < 4; j++)
                #pragma unroll
                for (int c = 0; c < 4; c++) acc[i][j][c] = 0.f;

        for (int kc = 0; kc < 8; kc++) {
            uint4 pre[2];
            if (kc < 7) {
                int k0n = (kc + 1) * 32;
                #pragma unroll
                for (int it = 0; it < 2; it++) {
                    int idx = it * TPB + tid;
                    int r = idx >> 2, c8 = idx & 3;
                    pre[it] = *(const uint4*)(Qm + (size_t)(n0 + r) * DD + k0n + c8 * 8);
                }
            }
            const uint32_t* bsb = BsU + buf * 2560;
            #pragma unroll
            for (int kt = 0; kt < 2; kt++) {
                int kw = kc * 16 + kt * 8;
                uint32_t a[4][4];
                #pragma unroll
                for (int i = 0; i < 4; i++) {
                    a[i][0] = AsU[rA0[i] + kw + tg];
                    a[i][1] = AsU[rA1[i] + kw + tg];
                    a[i][2] = AsU[rA0[i] + kw + 4 + tg];
                    a[i][3] = AsU[rA1[i] + kw + 4 + tg];
                }
                int kl = kt * 8 + tg;
                #pragma unroll
                for (int j = 0; j < 4; j++) {
                    uint32_t b0 = bsb[rB[j] + kl], b1 = bsb[rB[j] + kl + 4];
                    #pragma unroll
                    for (int i = 0; i < 4; i++)
                        mma_f16(acc[i][j][0], acc[i][j][1], acc[i][j][2], acc[i][j][3],
                                a[i][0], a[i][1], a[i][2], a[i][3], b0, b1);
                }
            }
            if (kc < 7) {
                #pragma unroll
                for (int it = 0; it < 2; it++) {
                    int idx = it * TPB + tid;
                    int r = idx >> 2, c8 = idx & 3;
                    uint32_t* p = BsU + (buf ^ 1) * 2560 + r * 20 + c8 * 4;
                    p[0] = pre[it].x; p[1] = pre[it].y; p[2] = pre[it].z; p[3] = pre[it].w;
                }
                __syncthreads();
                buf ^= 1;
            }
        }

        #pragma unroll
        for (int i = 0; i < 4; i++) {
            float s0 = 0.f, s1 = 0.f;
            #pragma unroll
            for (int j = 0; j < 4; j++) {
                s0 += __expf(acc[i][j][0] * INVT - INVT) + __expf(acc[i][j][1] * INVT - INVT);
                s1 += __expf(acc[i][j][2] * INVT - INVT) + __expf(acc[i][j][3] * INVT - INVT);
            }
            rp[i][0] += s0; rp[i][1] += s1;
        }
    }

    #pragma unroll
    for (int i = 0; i < 4; i++)
        #pragma unroll
        for (int h = 0; h < 2; h++) {
            float v = rp[i][h];
            v += __shfl_xor_sync(0xffffffffu, v, 1);
            v += __shfl_xor_sync(0xffffffffu, v, 2);
            if (tg == 0) red[(m0w + i*16 + h*8 + g) * 4 + wn] = v;
        }
    __syncthreads();
    if (tid < 128) {
        float s = red[tid*4+0] + red[tid*4+1] + red[tid*4+2] + red[tid*4+3];
        part[(size_t)(m0 + tid) * nch + chunk] = s;
    }
}

// ------- merged soft-assign + hard-argmax (view 1) -------
__global__ void k_assign(const float* __restrict__ logits,
                         const float* __restrict__ u_soft, const float* __restrict__ u_hard,
                         float* __restrict__ assign, float* __restrict__ outAsg) {
    __shared__ float sb[8]; __shared__ int si[8];
    int r = blockIdx.x, t = threadIdx.x;
    float zs[4], best = -1e30f; int bi = 0;
    #pragma unroll
    for (int j = 0; j < 4; j++) {
        int k = j * 256 + t;
        size_t i = (size_t)r * KK + k;
        float lg = logits[i];
        zs[j] = (lg + gumbelf_soft(u_soft[i])) * 2.0f;
        float zh = lg + gumbelf(u_hard[i]);
        if (zh > best) { best = zh; bi = k; }
    }
    float m = fmaxf(fmaxf(zs[0], zs[1]), fmaxf(zs[2], zs[3]));
    m = blockmax256(m);
    float s = 0.f;
    #pragma unroll
    for (int j = 0; j < 4; j++) { zs[j] = __expf(zs[j] - m); s += zs[j]; }
    s = blocksum256(s);
    float inv = 1.0f / s;
    #pragma unroll
    for (int j = 0; j < 4; j++)
        assign[(size_t)r * KK + j * 256 + t] = zs[j] * inv;
    #pragma unroll
    for (int o = 16; o; o >>= 1) {
        float ob = __shfl_xor_sync(0xffffffffu, best, o);
        int   oi = __shfl_xor_sync(0xffffffffu, bi, o);
        if (ob > best || (ob == best && oi < bi)) { best = ob; bi = oi; }
    }
    if ((t & 31) == 0) { sb[t >> 5] = best; si[t >> 5] = bi; }
    __syncthreads();
    if (t == 0) {
        #pragma unroll
        for (int w = 1; w < 8; w++)
            if (sb[w] > best || (sb[w] == best && si[w] < bi)) { best = sb[w]; bi = si[w]; }
        outAsg[r] = (float)bi;
    }
}

// ---------------- gumbel softmax (soft only, view 2) ----------------
__global__ void k_softmax(const float* __restrict__ logits, const float* __restrict__ u,
                          float* __restrict__ assign) {
    int r = blockIdx.x, t = threadIdx.x;
    float z[4];
    #pragma unroll
    for (int j = 0; j < 4; j++) {
        int k = j * 256 + t;
        size_t i = (size_t)r * KK + k;
        z[j] = (logits[i] + gumbelf_soft(u[i])) * 2.0f;
    }
    float m = fmaxf(fmaxf(z[0], z[1]), fmaxf(z[2], z[3]));
    m = blockmax256(m);
    float s = 0.f;
    #pragma unroll
    for (int j = 0; j < 4; j++) { z[j] = __expf(z[j] - m); s += z[j]; }
    s = blocksum256(s);
    float inv = 1.0f / s;
    #pragma unroll
    for (int j = 0; j < 4; j++)
        assign[(size_t)r * KK + j * 256 + t] = z[j] * inv;
}

// ---------------- column sums of assign (fp32 normalizer) ----------------
__global__ void k_colsum_part(const float* __restrict__ assign, float* __restrict__ csp) {
    int k = blockIdx.x * TPB + threadIdx.x;
    int c = blockIdx.y;
    float s = 0.f;
    #pragma unroll 4
    for (int b = c * (NB / CSCH); b < (c + 1) * (NB / CSCH); b++)
        s += assign[(size_t)b * KK + k];
    csp[(size_t)c * KK + k] = s;
}
__global__ void k_colsum_fin(const float* __restrict__ csp, float* __restrict__ norm) {
    int k = blockIdx.x * TPB + threadIdx.x;
    float s = 0.f;
    #pragma unroll
    for (int c = 0; c < CSCH; c++) s += csp[(size_t)c * KK + k];
    norm[k] = s;
}

// ---------------- agg_k finish ----------------
__global__ void k_aggk_finish(const float* __restrict__ part, const float* __restrict__ norm,
                              float* __restrict__ dst) {
    int r = blockIdx.x, t = threadIdx.x;
    float v = 0.f;
    #pragma unroll
    for (int s = 0; s < NSEG; s++) v += part[(size_t)s * KK * DD + (size_t)r * DD + t];
    v = v / (norm[r] + 1e-8f);
    float ss = blocksum256(v * v);
    dst[(size_t)r * DD + t] = v * rsqrtf(fmaxf(ss, 1e-12f));
}

// ------------- per-row CE -------------
__global__ void k_ce_row(const float* __restrict__ q, const float* __restrict__ kv,
                         const float* __restrict__ part, int nch,
                         float* __restrict__ lp) {
    int r = blockIdx.x, t = threadIdx.x;
    float v = q[(size_t)r * DD + t] * kv[(size_t)r * DD + t];
    float lpos = blocksum256(v);
    if (t == 0) {
        float S = expf(lpos * INVT - INVT);
        for (int c = 0; c < nch; c++) S += part[(size_t)r * nch + c];
        lp[r] = lpos * INVT - INVT - logf(S);
    }
}

// ---------------- final scalar loss ----------------
__global__ void k_loss(const float* __restrict__ lpn, const float* __restrict__ lpk,
                       float* __restrict__ out) {
    int t = threadIdx.x;
    float s1 = 0.f;
    for (int i = t; i < NB; i += TPB) s1 += lpn[i];
    s1 = blocksum256(s1);
    float s2 = 0.f;
    for (int i = t; i < KK; i += TPB) s2 += lpk[i];
    s2 = blocksum256(s2);
    if (t == 0) out[0] = -(s1 / NB) - (s2 / KK);
}

// ============================ launcher ============================
extern "C" void kernel_launch(void* const* d_in, const int* in_sizes, int n_in,
                              void* d_out, int out_size) {
    const float* x1    = (const float*)d_in[0];
    const float* x2    = (const float*)d_in[1];
    const float* W1    = (const float*)d_in[2];
    const float* W2    = (const float*)d_in[3];
    const float* ctx1r = (const float*)d_in[4];
    const float* ctx2r = (const float*)d_in[5];
    const float* qn_r  = (const float*)d_in[6];
    const float* qk_r  = (const float*)d_in[7];
    const float* u1a   = (const float*)d_in[8];
    const float* u1b   = (const float*)d_in[9];
    const float* u2a   = (const float*)d_in[10];
    const float* u2b   = (const float*)d_in[11];
    const float* qnz   = (const float*)d_in[12];
    (void)u2b; (void)in_sizes; (void)n_in; (void)out_size;

    cudaFuncSetAttribute(k_expsum_h, cudaFuncAttributeMaxDynamicSharedMemorySize, SMEM_H);
    cudaFuncSetAttribute(k_gemm_nth, cudaFuncAttributeMaxDynamicSharedMemorySize, SMEM_NTH);

    float* S;
    cudaGetSymbolAddress((void**)&S, g_scratch);
    __half* qn_h;  cudaGetSymbolAddress((void**)&qn_h,  g_qn_h);
    __half* qkq_h; cudaGetSymbolAddress((void**)&qkq_h, g_qkq_h);

    float* tmp    = S + O_TMP;
    float* feat1  = S + O_FEAT1;
    float* ctx1   = S + O_CTX1;
    float* ctx2   = S + O_CTX2;
    float* logits = S + O_LOGITS;
    float* assign = S + O_ASSIGN;
    float* aggk1  = S + O_AGGK1;
    float* aggp   = S + O_AGGP;
    float* csp    = S + O_CSP;
    float* normk  = S + O_NORMK;
    float* lpn    = S + O_LPN;
    float* lpk    = S + O_LPK;
    float* partn  = S + O_PARTN;
    float* partk  = S + O_PARTK;
    float* w1t    = S + O_W1T;
    float* w2t    = S + O_W2T;

    float* outF     = (float*)d_out;
    float* outAsg   = outF;
    float* feat2    = outF + NB;
    float* aggk2    = outF + NB + (size_t)NB * DD;
    float* outLoss  = outF + NB + (size_t)NB * DD + (size_t)KK * DD;

    k_transpose<<<dim3(DD/32, DIN/32), dim3(32, 8)>>>(W1, w1t, DIN, DD);
    k_transpose<<<dim3(DD/32, DIN/32), dim3(32, 8)>>>(W2, w2t, DIN, DD);

    k_gemm_nth<<<dim3(32, 2), TPB, SMEM_NTH>>>(x1, w1t, tmp, DIN, DD);
    k_rownorm_w<<<NB/8, TPB>>>(tmp, feat1);
    k_gemm_nth<<<dim3(32, 2), TPB, SMEM_NTH>>>(x2, w2t, tmp, DIN, DD);
    k_rownorm_w<<<NB/8, TPB>>>(tmp, feat2);
    k_rownorm_w<<<KK/8, TPB>>>(ctx1r, ctx1);
    k_rownorm_w<<<KK/8, TPB>>>(ctx2r, ctx2);
    k_rownorm_w_h<<<LL/8, TPB>>>(qn_r, qn_h);
    k_rownorm_queue_w_h<<<QKR/8, TPB>>>(qk_r, qnz, qkq_h);

    // view 1
    k_gemm_nth<<<dim3(32, 8), TPB, SMEM_NTH>>>(feat1, ctx1, logits, DD, KK);
    k_assign<<<NB, TPB>>>(logits, u1a, u1b, assign, outAsg);
    k_colsum_part<<<dim3(KK / TPB, CSCH), TPB>>>(assign, csp);
    k_colsum_fin<<<KK / TPB, TPB>>>(csp, normk);
    k_aggk_h<<<dim3(8, 2, NSEG), TPB>>>(assign, feat1, aggp);
    k_aggk_finish<<<KK, TPB>>>(aggp, normk, aggk1);

    // view 2
    k_gemm_nth<<<dim3(32, 8), TPB, SMEM_NTH>>>(feat2, ctx2, logits, DD, KK);
    k_softmax<<<NB, TPB>>>(logits, u2a, assign);
    k_colsum_part<<<dim3(KK / TPB, CSCH), TPB>>>(assign, csp);
    k_colsum_fin<<<KK / TPB, TPB>>>(csp, normk);
    k_aggk_h<<<dim3(8, 2, NSEG), TPB>>>(assign, feat2, aggp);
    k_aggk_finish<<<KK, TPB>>>(aggp, normk, aggk2);

    // losses
    k_expsum_h<<<dim3(NB / 128, NCHN), TPB, SMEM_H>>>(feat1, qn_h, partn, TPCN, NCHN);
    k_ce_row<<<NB, TPB>>>(feat1, feat2, partn, NCHN, lpn);
    k_expsum_h<<<dim3(KK / 128, NCHK), TPB, SMEM_H>>>(aggk1, qkq_h, partk, TPCK, NCHK);
    k_ce_row<<<KK, TPB>>>(aggk1, aggk2, partk, NCHK, lpk);

    k_loss<<<1, TPB>>>(lpn, lpk, outLoss);
}